// round 2
// baseline (speedup 1.0000x reference)
#include <cuda_runtime.h>

// ---------------------------------------------------------------------------
// Packed f32x2 helpers (Blackwell FFMA2 path — 2x fp32 FMA throughput)
// ---------------------------------------------------------------------------
static __device__ __forceinline__ void ffma2(unsigned long long &d,
                                             unsigned long long a,
                                             unsigned long long b) {
    asm("fma.rn.f32x2 %0, %1, %2, %0;" : "+l"(d) : "l"(a), "l"(b));
}
static __device__ __forceinline__ unsigned long long splat2(float f) {
    unsigned long long r;
    asm("mov.b64 %0, {%1, %1};" : "=l"(r) : "f"(f));
    return r;
}
static __device__ __forceinline__ void unpack2(unsigned long long v, float &lo, float &hi) {
    asm("mov.b64 {%0, %1}, %2;" : "=f"(lo), "=f"(hi) : "l"(v));
}

// ---------------------------------------------------------------------------
// Static scratch pool (no cudaMalloc allowed).
// ---------------------------------------------------------------------------
#define POOL_FLOATS 420000000LL
__device__ float g_pool[POOL_FLOATS];

enum { M_BLOCK = 0, M_RES = 1, M_RED = 2 };

constexpr int TILE = 256;

// Accumulate 4 input channels against W rows staged in shared memory.
// W reads are warp-uniform broadcasts (LDS.128, 1 wavefront each).
template<int COUT>
static __device__ __forceinline__ void accum4(float4 f,
                                              const float* __restrict__ wrow,
                                              unsigned long long* acc) {
    const float fv[4] = {f.x, f.y, f.z, f.w};
#pragma unroll
    for (int u = 0; u < 4; u++) {
        unsigned long long fp = splat2(fv[u]);
        const ulonglong2* w2 = reinterpret_cast<const ulonglong2*>(wrow + u * COUT);
#pragma unroll
        for (int j = 0; j < COUT / 4; j++) {
            ulonglong2 wv = w2[j];
            ffma2(acc[2 * j + 0], fp, wv.x);
            ffma2(acc[2 * j + 1], fp, wv.y);
        }
    }
}

// ---------------------------------------------------------------------------
// Fused sparse gather-conv, cooperative-gather version.
//   out[r] = epilogue( sum_{k, nbr[r][k]>=0} cat(featA,featB)[nbr[r][k]] @ W[k] )
// Per k (and per concat phase): 256 threads cooperatively gather 256 neighbor
// rows into smem (coalesced: one feat row = 1-2 full 128B lines), zero-filling
// missing neighbors, then each thread computes its own output row densely.
// ---------------------------------------------------------------------------
template<int CINA, int CINB, int COUT, int MODE>
__global__ void __launch_bounds__(256)
conv_kernel(const float* __restrict__ featA, const float* __restrict__ featB,
            const int* __restrict__ nbr, const float* __restrict__ W,
            const float* __restrict__ sb, const float* __restrict__ res,
            float* __restrict__ out, int N) {
    static_assert(CINB == 0 || CINB == CINA, "phases must be equal-sized");
    constexpr int CH = CINA;                       // channels per phase
    constexpr int CIN = CINA + CINB;
    constexpr int PAD = ((((CH + 4) / 4) % 2) == 1) ? 4 : 8;  // odd 16B-unit stride
    constexpr int STR = CH + PAD;                  // smem row stride (floats)
    constexpr int NPHASE = (CINB > 0) ? 2 : 1;
    constexpr int PARTS = CH / 4;                  // float4 parts per row

    extern __shared__ __align__(16) float smem[];
    float* sW = smem;                              // CH * COUT floats
    float* sF = sW + CH * COUT;                    // TILE * STR floats
    int*   sI = (int*)(sF + TILE * STR);           // TILE * 27 ints

    const int tid = threadIdx.x;
    const long long r0 = (long long)blockIdx.x * TILE;
    const long long NI = (long long)N * 27;

    // Stage neighbor indices for this block's 256 rows (fully coalesced).
    for (int i = tid; i < TILE * 27; i += 256) {
        long long g = r0 * 27 + i;
        sI[i] = (g < NI) ? nbr[g] : -1;
    }

    unsigned long long acc[COUT / 2];
#pragma unroll
    for (int j = 0; j < COUT / 2; j++) acc[j] = 0ULL;

    for (int k = 0; k < 27; k++) {
#pragma unroll 1
        for (int ph = 0; ph < NPHASE; ph++) {
            __syncthreads();  // previous phase's sW/sF reads done (also orders sI)
            // Stage W chunk [CH x COUT] for this k / phase.
            {
                const float4* wg = reinterpret_cast<const float4*>(
                    W + ((long long)k * CIN + (long long)ph * CINA) * COUT);
                for (int i = tid; i < CH * COUT / 4; i += 256)
                    reinterpret_cast<float4*>(sW)[i] = wg[i];
            }
            // Cooperative gather: PARTS threads per row -> contiguous 128B lines.
            {
                const float* fsrc = ph ? featB : featA;
                for (int s = tid; s < TILE * PARTS; s += 256) {
                    const int row = s / PARTS;
                    const int part = s - row * PARTS;
                    const int idx = sI[row * 27 + k];
                    float4 v = make_float4(0.f, 0.f, 0.f, 0.f);
                    if (idx >= 0)
                        v = reinterpret_cast<const float4*>(fsrc + (long long)idx * CH)[part];
                    reinterpret_cast<float4*>(sF + row * STR)[part] = v;
                }
            }
            __syncthreads();
            // Dense compute: thread tid owns output row r0+tid.
            const float4* frow = reinterpret_cast<const float4*>(sF + tid * STR);
#pragma unroll 2
            for (int c4 = 0; c4 < CH / 4; c4++) {
                float4 f = frow[c4];
                accum4<COUT>(f, sW + (c4 * 4) * COUT, acc);
            }
        }
    }

    const long long r = r0 + tid;
    if (r >= N) return;

    const float* scale = sb;
    const float* bias  = sb + COUT;
    float* o = out + r * COUT;
    const float* resr = (MODE == M_RES) ? (res + r * COUT) : nullptr;
    const float* cA = featA + r * CINA;            // for M_RED (cat row r)
    const float* cB = (CINB > 0) ? (featB + r * CINB) : nullptr;

#pragma unroll
    for (int j = 0; j < COUT / 2; j++) {
        float a0, a1;
        unpack2(acc[j], a0, a1);
        const int c0 = 2 * j, c1 = 2 * j + 1;
        float v0 = a0 * scale[c0] + bias[c0];
        float v1 = a1 * scale[c1] + bias[c1];
        if constexpr (MODE == M_RES) {
            v0 += resr[c0];
            v1 += resr[c1];
        }
        v0 = fmaxf(v0, 0.0f);
        v1 = fmaxf(v1, 0.0f);
        if constexpr (MODE == M_RED) {
            // reduce(cat)[c] = cat[2c] + cat[2c+1]; cat = [featA_row | featB_row]
#pragma unroll
            for (int t = 0; t < 2; t++) {
                const int c = (t == 0) ? c0 : c1;
                float rsum;
                if (2 * c + 1 < CINA) {
                    rsum = cA[2 * c] + cA[2 * c + 1];
                } else {
                    rsum = cB[2 * c - CINA] + cB[2 * c + 1 - CINA];
                }
                if (t == 0) v0 += rsum; else v1 += rsum;
            }
        }
        o[c0] = v0;
        o[c1] = v1;
    }
}

// ---------------------------------------------------------------------------
// Host orchestration
// ---------------------------------------------------------------------------
static inline size_t smem_bytes_for(int CH, int COUT) {
    int pad = ((((CH + 4) / 4) % 2) == 1) ? 4 : 8;
    return (size_t)(CH * COUT + TILE * (CH + pad)) * 4 + (size_t)TILE * 27 * 4;
}

#define LAUNCH(CA, CB, CO, MO, fa, fb, nb, wp, sbp, rs, op, n)                       \
    do {                                                                             \
        auto kfn = conv_kernel<CA, CB, CO, MO>;                                      \
        size_t sh = smem_bytes_for(CA, CO);                                          \
        cudaFuncSetAttribute(kfn, cudaFuncAttributeMaxDynamicSharedMemorySize,       \
                             (int)sh);                                               \
        kfn<<<dim3((unsigned)(((n) + TILE - 1) / TILE)), 256, sh>>>(                 \
            fa, fb, nb, wp, sbp, rs, op, n);                                         \
    } while (0)

extern "C" void kernel_launch(void* const* d_in, const int* in_sizes, int n_in,
                              void* d_out, int out_size) {
    (void)n_in; (void)out_size;
    const float* vf     = (const float*)d_in[0];
    const float* Win    = (const float*)d_in[1];
    const float* W32    = (const float*)d_in[2];
    const float* W64    = (const float*)d_in[3];
    const float* Wd3    = (const float*)d_in[4];
    const float* W6432  = (const float*)d_in[5];
    const float* W12864 = (const float*)d_in[6];
    const float* bn32   = (const float*)d_in[7];
    const float* bn64   = (const float*)d_in[8];
    const int* nbr1  = (const int*)d_in[9];
    const int* nbr2  = (const int*)d_in[10];
    const int* nbr3  = (const int*)d_in[11];
    const int* nbr4  = (const int*)d_in[12];
    const int* nbrd2 = (const int*)d_in[13];
    const int* nbrd3 = (const int*)d_in[14];
    const int* nbrd4 = (const int*)d_in[15];
    const int* nbri4 = (const int*)d_in[16];
    const int* nbri3 = (const int*)d_in[17];
    const int* nbri2 = (const int*)d_in[18];

    const int N1 = in_sizes[9]  / 27;
    const int N2 = in_sizes[10] / 27;
    const int N3 = in_sizes[11] / 27;
    const int N4 = in_sizes[12] / 27;

    float* pool = nullptr;
    cudaGetSymbolAddress((void**)&pool, g_pool);
    size_t off = 0;
    auto alloc = [&](size_t nfloats) { float* p = pool + off; off += nfloats; return p; };

    float* L1a = alloc((size_t)N1 * 32);
    float* L1b = alloc((size_t)N1 * 32);
    float* L1c = alloc((size_t)N1 * 32);
    float* L1d = alloc((size_t)N1 * 32);
    float* L1e = alloc((size_t)N1 * 32);
    float* L2a = alloc((size_t)N2 * 32);
    float* L2b = alloc((size_t)N2 * 32);
    float* L2c = alloc((size_t)N2 * 32);
    float* L2d = alloc((size_t)N2 * 32);
    float* L3a = alloc((size_t)N3 * 64);
    float* L3b = alloc((size_t)N3 * 64);
    float* L3c = alloc((size_t)N3 * 64);
    float* L3d = alloc((size_t)N3 * 64);
    float* L4a = alloc((size_t)N4 * 64);
    float* L4b = alloc((size_t)N4 * 64);
    float* L4c = alloc((size_t)N4 * 64);

    const long long W32S = 27LL * 32 * 32;
    const long long W64S = 27LL * 64 * 64;
    const long long W6432S = 27LL * 64 * 32;
    const long long W12864S = 27LL * 128 * 64;
    auto b32 = [&](int j) { return bn32 + (long long)j * 64; };
    auto b64 = [&](int j) { return bn64 + (long long)j * 128; };

    // ---- Encoder ----
    LAUNCH(4, 0, 32, M_BLOCK, vf, nullptr, nbr1, Win, b32(0), nullptr, L1a, N1);
    LAUNCH(32, 0, 32, M_BLOCK, L1a, nullptr, nbr1, W32 + 0 * W32S, b32(1), nullptr, L1b, N1);   // x1
    LAUNCH(32, 0, 32, M_BLOCK, L1b, nullptr, nbrd2, W32 + 1 * W32S, b32(2), nullptr, L2a, N2);
    LAUNCH(32, 0, 32, M_BLOCK, L2a, nullptr, nbr2, W32 + 2 * W32S, b32(3), nullptr, L2b, N2);
    LAUNCH(32, 0, 32, M_BLOCK, L2b, nullptr, nbr2, W32 + 3 * W32S, b32(4), nullptr, L2a, N2);   // x2
    LAUNCH(32, 0, 64, M_BLOCK, L2a, nullptr, nbrd3, Wd3, b64(0), nullptr, L3a, N3);
    LAUNCH(64, 0, 64, M_BLOCK, L3a, nullptr, nbr3, W64 + 0 * W64S, b64(1), nullptr, L3b, N3);
    LAUNCH(64, 0, 64, M_BLOCK, L3b, nullptr, nbr3, W64 + 1 * W64S, b64(2), nullptr, L3a, N3);   // x3
    LAUNCH(64, 0, 64, M_BLOCK, L3a, nullptr, nbrd4, W64 + 2 * W64S, b64(3), nullptr, L4a, N4);
    LAUNCH(64, 0, 64, M_BLOCK, L4a, nullptr, nbr4, W64 + 3 * W64S, b64(4), nullptr, L4b, N4);
    LAUNCH(64, 0, 64, M_BLOCK, L4b, nullptr, nbr4, W64 + 4 * W64S, b64(5), nullptr, L4a, N4);   // x4

    // ---- Bottom: basic(x4) + concat conv + reduce ----
    LAUNCH(64, 0, 64, M_BLOCK, L4a, nullptr, nbr4, W64 + 5 * W64S, b64(6), nullptr, L4b, N4);
    LAUNCH(64, 0, 64, M_RES, L4b, nullptr, nbr4, W64 + 6 * W64S, b64(7), L4a, L4c, N4);         // t
    LAUNCH(64, 64, 64, M_RED, L4a, L4c, nbr4, W12864 + 0 * W12864S, b64(11), nullptr, L4b, N4); // x

    // ---- Decoder level 3 ----
    LAUNCH(64, 0, 64, M_BLOCK, L4b, nullptr, nbri4, W64 + 7 * W64S, b64(8), nullptr, L3b, N3);  // xu4
    LAUNCH(64, 0, 64, M_BLOCK, L3a, nullptr, nbr3, W64 + 8 * W64S, b64(9), nullptr, L3c, N3);
    LAUNCH(64, 0, 64, M_RES, L3c, nullptr, nbr3, W64 + 9 * W64S, b64(10), L3a, L3d, N3);        // t
    LAUNCH(64, 64, 64, M_RED, L3b, L3d, nbr3, W12864 + 1 * W12864S, b64(12), nullptr, L3c, N3); // x

    // ---- Decoder level 2 ----
    LAUNCH(64, 0, 32, M_BLOCK, L3c, nullptr, nbri3, W6432 + 0 * W6432S, b32(11), nullptr, L2b, N2); // xu3
    LAUNCH(32, 0, 32, M_BLOCK, L2a, nullptr, nbr2, W32 + 4 * W32S, b32(5), nullptr, L2c, N2);
    LAUNCH(32, 0, 32, M_RES, L2c, nullptr, nbr2, W32 + 5 * W32S, b32(6), L2a, L2d, N2);             // t
    LAUNCH(32, 32, 32, M_RED, L2b, L2d, nbr2, W6432 + 1 * W6432S, b32(12), nullptr, L2c, N2);       // x

    // ---- Decoder level 1 ----
    LAUNCH(32, 0, 32, M_BLOCK, L2c, nullptr, nbri2, W32 + 6 * W32S, b32(7), nullptr, L1c, N1);  // xu2
    LAUNCH(32, 0, 32, M_BLOCK, L1b, nullptr, nbr1, W32 + 7 * W32S, b32(8), nullptr, L1d, N1);
    LAUNCH(32, 0, 32, M_RES, L1d, nullptr, nbr1, W32 + 8 * W32S, b32(9), L1b, L1e, N1);         // t
    LAUNCH(32, 32, 32, M_RED, L1c, L1e, nbr1, W6432 + 2 * W6432S, b32(13), nullptr, L1d, N1);   // x

    // ---- Output ----
    LAUNCH(32, 0, 32, M_BLOCK, L1d, nullptr, nbr1, W32 + 9 * W32S, b32(10), nullptr,
           (float*)d_out, N1);
}

// round 5
// speedup vs baseline: 2.6989x; 2.6989x over previous
#include <cuda_runtime.h>
#include <cuda_bf16.h>
#include <cstdint>

// ---------------------------------------------------------------------------
// Static scratch pool (no cudaMalloc allowed).
// ---------------------------------------------------------------------------
#define POOL_FLOATS 420000000LL
__device__ __align__(1024) float g_pool[POOL_FLOATS];

enum { M_BLOCK = 0, M_RES = 1, M_RED = 2 };

// ---------------------------------------------------------------------------
// Baseline-PTX tensor helpers (sm_80-era: ldmatrix + mma.sync, compile on
// compute_103 — tcgen05 is NOT available under this harness's PTX target).
// ---------------------------------------------------------------------------
static __device__ __forceinline__ uint32_t smem_u32_of(const void* p) {
    uint32_t a;
    asm("{ .reg .u64 t; cvta.to.shared.u64 t, %1; cvt.u32.u64 %0, t; }" : "=r"(a) : "l"(p));
    return a;
}
static __device__ __forceinline__ void ldm_x4(uint32_t* r, uint32_t addr) {
    asm volatile("ldmatrix.sync.aligned.m8n8.x4.shared.b16 {%0,%1,%2,%3}, [%4];"
                 : "=r"(r[0]), "=r"(r[1]), "=r"(r[2]), "=r"(r[3]) : "r"(addr));
}
static __device__ __forceinline__ void ldm_x2(uint32_t* r, uint32_t addr) {
    asm volatile("ldmatrix.sync.aligned.m8n8.x2.shared.b16 {%0,%1}, [%2];"
                 : "=r"(r[0]), "=r"(r[1]) : "r"(addr));
}
// D[16x8] += A[16x16](bf16,row) * B[16x8](bf16,col)
static __device__ __forceinline__ void mma16816(float* c, const uint32_t* a, const uint32_t* b) {
    asm volatile(
        "mma.sync.aligned.m16n8k16.row.col.f32.bf16.bf16.f32 "
        "{%0,%1,%2,%3}, {%4,%5,%6,%7}, {%8,%9}, {%0,%1,%2,%3};"
        : "+f"(c[0]), "+f"(c[1]), "+f"(c[2]), "+f"(c[3])
        : "r"(a[0]), "r"(a[1]), "r"(a[2]), "r"(a[3]), "r"(b[0]), "r"(b[1]));
}
// Split (x,y) into packed bf16x2 hi and lo (residual) words. Element 0 in low 16.
static __device__ __forceinline__ void split2(float x, float y, uint32_t& hi, uint32_t& lo) {
    asm("cvt.rn.bf16x2.f32 %0, %1, %2;" : "=r"(hi) : "f"(y), "f"(x));
    float hx = __uint_as_float(hi << 16);
    float hy = __uint_as_float(hi & 0xffff0000u);
    asm("cvt.rn.bf16x2.f32 %0, %1, %2;" : "=r"(lo) : "f"(y - hy), "f"(x - hx));
}

// ---------------------------------------------------------------------------
// Weight prep: W[27][CINtot][COUT] f32 slice -> dst[(k)][{hi,lo}][COUT][CPAD] bf16
// (B^T layout: row n = output channel, col c = input channel; zero-pad c>=CIN)
// ---------------------------------------------------------------------------
__global__ void prep_w_kernel(const float* __restrict__ Wsrc, __nv_bfloat16* __restrict__ dst,
                              int CIN, int CINtot, int cin_off, int COUT, int CPAD) {
    int t = blockIdx.x * blockDim.x + threadIdx.x;
    if (t >= 27 * COUT) return;
    int k = t / COUT, n = t - k * COUT;
    const float* w = Wsrc + ((size_t)k * CINtot + cin_off) * COUT + n;
    __nv_bfloat16* dhi = dst + (size_t)k * 2 * COUT * CPAD + (size_t)n * CPAD;
    __nv_bfloat16* dlo = dhi + (size_t)COUT * CPAD;
    for (int c = 0; c < CPAD; c++) {
        float v = (c < CIN) ? w[(size_t)c * COUT] : 0.0f;
        __nv_bfloat16 h = __float2bfloat16(v);
        float hf = __bfloat162float(h);
        dhi[c] = h;
        dlo[c] = __float2bfloat16(v - hf);
    }
}

// ---------------------------------------------------------------------------
// Sparse gather-conv via mma.sync bf16 split precision (3 MMAs ~ fp32).
// CTA = 128 rows, 4 warps (32 rows each). acc[2][COUT/8][4] in registers.
// ---------------------------------------------------------------------------
template<int CIN, int NPHASE, int COUT, int MODE>
__global__ void __launch_bounds__(128)
conv_mma_kernel(const float* __restrict__ featA, const float* __restrict__ featB,
                const int* __restrict__ nbr, const __nv_bfloat16* __restrict__ Bw,
                const float* __restrict__ sb, const float* __restrict__ res,
                float* __restrict__ out, int N) {
    constexpr int KS = (CIN + 15) / 16;          // 16-wide K steps
    constexpr int CPAD = KS * 16;
    constexpr int STR = CPAD + 8;                // smem row stride in halves
    constexpr int PARTS = (CIN >= 4) ? CIN / 4 : 1;   // float4 parts per feat row
    constexpr int LOGP = (PARTS == 1) ? 0 : (PARTS == 8) ? 3 : 4;
    constexpr int NT = COUT / 8;                 // n-tiles per warp

    constexpr uint32_t A_TILE = 128 * STR * 2;   // bytes per A tile
    constexpr uint32_t B_TILE = (uint32_t)COUT * STR * 2;
    constexpr uint32_t OFF_AHI = 0;
    constexpr uint32_t OFF_ALO = A_TILE;
    constexpr uint32_t OFF_BHI = 2 * A_TILE;
    constexpr uint32_t OFF_BLO = 2 * A_TILE + B_TILE;
    constexpr uint32_t OFF_NBR = 2 * A_TILE + 2 * B_TILE;

    extern __shared__ __align__(16) char smem[];
    const uint32_t sbase = smem_u32_of(smem);
    int* sNbr = (int*)(smem + OFF_NBR);

    const int tid = threadIdx.x;
    const int wid = tid >> 5;
    const int lane = tid & 31;
    const long long r0 = (long long)blockIdx.x * 128;

    // Zero-fill A tiles once if K is padded (CIN=4 case): pad cols never rewritten.
    if constexpr (CIN < CPAD) {
        for (int i = tid; i < (int)(2 * A_TILE / 16); i += 128)
            ((float4*)smem)[i] = make_float4(0.f, 0.f, 0.f, 0.f);
    }
    // Stage neighbor table (coalesced).
    const long long NI = (long long)N * 27;
    for (int i = tid; i < 128 * 27; i += 128) {
        long long g = r0 * 27 + i;
        sNbr[i] = (g < NI) ? nbr[g] : -1;
    }

    float acc[2][NT][4];
#pragma unroll
    for (int rt = 0; rt < 2; rt++)
#pragma unroll
        for (int j = 0; j < NT; j++)
#pragma unroll
            for (int u = 0; u < 4; u++) acc[rt][j][u] = 0.0f;

    for (int k = 0; k < 27; k++) {
#pragma unroll 1
        for (int ph = 0; ph < NPHASE; ph++) {
            __syncthreads();  // previous iteration's smem reads complete

            // Stage B hi+lo [COUT][CPAD] -> padded smem rows.
            {
                const __nv_bfloat16* src = Bw + (size_t)(ph * 27 + k) * (2 * COUT * CPAD);
                constexpr int UPW = CPAD / 8;  // 16B units per row
                for (int i = tid; i < 2 * COUT * UPW; i += 128) {
                    const int tile = i / (COUT * UPW);
                    const int rem = i - tile * (COUT * UPW);
                    const int row = rem / UPW;
                    const int u = rem - row * UPW;
                    float4 v = ((const float4*)(src + (size_t)tile * COUT * CPAD +
                                                (size_t)row * CPAD))[u];
                    *(float4*)(smem + (tile ? OFF_BLO : OFF_BHI) +
                               ((uint32_t)row * STR + (uint32_t)u * 8) * 2) = v;
                }
            }
            // Gather A rows -> bf16 hi/lo split, padded smem rows.
            {
                const float* fsrc = (NPHASE > 1 && ph) ? featB : featA;
                for (int s = tid; s < 128 * PARTS; s += 128) {
                    const int row = s >> LOGP;
                    const int part = s & (PARTS - 1);
                    const int idx = sNbr[row * 27 + k];
                    float4 v = make_float4(0.f, 0.f, 0.f, 0.f);
                    if (idx >= 0)
                        v = ((const float4*)(fsrc + (size_t)idx * CIN))[part];
                    uint32_t h0, l0, h1, l1;
                    split2(v.x, v.y, h0, l0);
                    split2(v.z, v.w, h1, l1);
                    const uint32_t off = ((uint32_t)row * STR + (uint32_t)part * 4) * 2;
                    asm volatile("st.shared.v2.b32 [%0], {%1,%2};"
                                 :: "r"(sbase + OFF_AHI + off), "r"(h0), "r"(h1) : "memory");
                    asm volatile("st.shared.v2.b32 [%0], {%1,%2};"
                                 :: "r"(sbase + OFF_ALO + off), "r"(l0), "r"(l1) : "memory");
                }
            }
            __syncthreads();

            // Dense MMA accumulate.
            const uint32_t rowbase = (uint32_t)wid * 32;
#pragma unroll
            for (int s = 0; s < KS; s++) {
                uint32_t ahi[2][4], alo[2][4];
#pragma unroll
                for (int rt = 0; rt < 2; rt++) {
                    const uint32_t arow = rowbase + rt * 16 + (lane & 15);
                    const uint32_t acol = (uint32_t)s * 16 + ((lane >> 4) << 3);
                    const uint32_t aoff = (arow * STR + acol) * 2;
                    ldm_x4(ahi[rt], sbase + OFF_AHI + aoff);
                    ldm_x4(alo[rt], sbase + OFF_ALO + aoff);
                }
#pragma unroll
                for (int j = 0; j < NT; j++) {
                    const uint32_t brow = (uint32_t)j * 8 + (lane & 7);
                    const uint32_t bcol = (uint32_t)s * 16 + ((lane & 8) ? 8u : 0u);
                    const uint32_t boff = (brow * STR + bcol) * 2;
                    uint32_t bhi[2], blo[2];
                    ldm_x2(bhi, sbase + OFF_BHI + boff);
                    ldm_x2(blo, sbase + OFF_BLO + boff);
#pragma unroll
                    for (int rt = 0; rt < 2; rt++) {
                        mma16816(acc[rt][j], ahi[rt], bhi);
                        mma16816(acc[rt][j], ahi[rt], blo);
                        mma16816(acc[rt][j], alo[rt], bhi);
                    }
                }
            }
        }
    }

    // Epilogue. Fragment (rt, j): c0,c1 -> row rt*16 + lane/4, cols n0,n0+1;
    // c2,c3 -> row +8.
    const float* scale = sb;
    const float* bias = sb + COUT;
#pragma unroll
    for (int j = 0; j < NT; j++) {
        const int n0 = j * 8 + 2 * (lane & 3);
        const float sc0 = scale[n0], sc1 = scale[n0 + 1];
        const float bi0 = bias[n0], bi1 = bias[n0 + 1];
#pragma unroll
        for (int rt = 0; rt < 2; rt++)
#pragma unroll
            for (int h = 0; h < 2; h++) {
                const long long r = r0 + wid * 32 + rt * 16 + (lane >> 2) + h * 8;
                if (r >= N) continue;
                float v0 = acc[rt][j][2 * h + 0] * sc0 + bi0;
                float v1 = acc[rt][j][2 * h + 1] * sc1 + bi1;
                if constexpr (MODE == M_RES) {
                    v0 += res[r * COUT + n0];
                    v1 += res[r * COUT + n0 + 1];
                }
                v0 = fmaxf(v0, 0.0f);
                v1 = fmaxf(v1, 0.0f);
                if constexpr (MODE == M_RED) {
                    const float* cA = featA + r * CIN;
                    const float* cB = featB + r * CIN;
#pragma unroll
                    for (int u = 0; u < 2; u++) {
                        const int c = n0 + u;
                        float rsum = (2 * c + 1 < CIN)
                                         ? cA[2 * c] + cA[2 * c + 1]
                                         : cB[2 * c - CIN] + cB[2 * c + 1 - CIN];
                        if (u == 0) v0 += rsum; else v1 += rsum;
                    }
                }
                *(float2*)(out + r * COUT + n0) = make_float2(v0, v1);
            }
    }
}

// ---------------------------------------------------------------------------
// Host orchestration
// ---------------------------------------------------------------------------
#define CONV(CIN_, NPH_, CO_, MO_, fa, fb, nb, Wsrc, sbp, rs, op, n)                          \
    do {                                                                                      \
        constexpr int KS_ = ((CIN_) + 15) / 16;                                               \
        constexpr int CPAD_ = KS_ * 16;                                                       \
        constexpr int STR_ = CPAD_ + 8;                                                       \
        __nv_bfloat16* bw = (__nv_bfloat16*)alloc((size_t)(NPH_) * 27 * (CO_) * CPAD_);       \
        for (int ph = 0; ph < (NPH_); ph++)                                                   \
            prep_w_kernel<<<(27 * (CO_) + 127) / 128, 128>>>(                                 \
                Wsrc, bw + (size_t)ph * 27 * 2 * (CO_) * CPAD_, CIN_, (CIN_) * (NPH_),        \
                ph * (CIN_), CO_, CPAD_);                                                     \
        auto kfn = conv_mma_kernel<CIN_, NPH_, CO_, MO_>;                                     \
        constexpr size_t sh = (size_t)(2 * 128 * STR_ + 2 * (CO_) * STR_) * 2 +               \
                              (size_t)128 * 27 * 4;                                           \
        cudaFuncSetAttribute(kfn, cudaFuncAttributeMaxDynamicSharedMemorySize, (int)sh);      \
        kfn<<<(unsigned)(((n) + 127) / 128), 128, sh>>>(fa, fb, nb, bw, sbp, rs, op, n);      \
    } while (0)

extern "C" void kernel_launch(void* const* d_in, const int* in_sizes, int n_in,
                              void* d_out, int out_size) {
    (void)n_in; (void)out_size;
    const float* vf     = (const float*)d_in[0];
    const float* Win    = (const float*)d_in[1];
    const float* W32    = (const float*)d_in[2];
    const float* W64    = (const float*)d_in[3];
    const float* Wd3    = (const float*)d_in[4];
    const float* W6432  = (const float*)d_in[5];
    const float* W12864 = (const float*)d_in[6];
    const float* bn32   = (const float*)d_in[7];
    const float* bn64   = (const float*)d_in[8];
    const int* nbr1  = (const int*)d_in[9];
    const int* nbr2  = (const int*)d_in[10];
    const int* nbr3  = (const int*)d_in[11];
    const int* nbr4  = (const int*)d_in[12];
    const int* nbrd2 = (const int*)d_in[13];
    const int* nbrd3 = (const int*)d_in[14];
    const int* nbrd4 = (const int*)d_in[15];
    const int* nbri4 = (const int*)d_in[16];
    const int* nbri3 = (const int*)d_in[17];
    const int* nbri2 = (const int*)d_in[18];

    const int N1 = in_sizes[9]  / 27;
    const int N2 = in_sizes[10] / 27;
    const int N3 = in_sizes[11] / 27;
    const int N4 = in_sizes[12] / 27;

    float* pool = nullptr;
    cudaGetSymbolAddress((void**)&pool, g_pool);
    size_t off = 0;
    auto alloc = [&](size_t nfloats) {
        float* p = pool + off;
        off += (nfloats + 255) & ~(size_t)255;
        return p;
    };

    float* L1a = alloc((size_t)N1 * 32);
    float* L1b = alloc((size_t)N1 * 32);
    float* L1c = alloc((size_t)N1 * 32);
    float* L1d = alloc((size_t)N1 * 32);
    float* L1e = alloc((size_t)N1 * 32);
    float* L2a = alloc((size_t)N2 * 32);
    float* L2b = alloc((size_t)N2 * 32);
    float* L2c = alloc((size_t)N2 * 32);
    float* L2d = alloc((size_t)N2 * 32);
    float* L3a = alloc((size_t)N3 * 64);
    float* L3b = alloc((size_t)N3 * 64);
    float* L3c = alloc((size_t)N3 * 64);
    float* L3d = alloc((size_t)N3 * 64);
    float* L4a = alloc((size_t)N4 * 64);
    float* L4b = alloc((size_t)N4 * 64);
    float* L4c = alloc((size_t)N4 * 64);

    const long long W32S = 27LL * 32 * 32;
    const long long W64S = 27LL * 64 * 64;
    const long long W6432S = 27LL * 64 * 32;
    const long long W12864S = 27LL * 128 * 64;
    auto b32 = [&](int j) { return bn32 + (long long)j * 64; };
    auto b64 = [&](int j) { return bn64 + (long long)j * 128; };

    // ---- Encoder ----
    CONV(4, 1, 32, M_BLOCK, vf, nullptr, nbr1, Win, b32(0), nullptr, L1a, N1);
    CONV(32, 1, 32, M_BLOCK, L1a, nullptr, nbr1, W32 + 0 * W32S, b32(1), nullptr, L1b, N1);   // x1
    CONV(32, 1, 32, M_BLOCK, L1b, nullptr, nbrd2, W32 + 1 * W32S, b32(2), nullptr, L2a, N2);
    CONV(32, 1, 32, M_BLOCK, L2a, nullptr, nbr2, W32 + 2 * W32S, b32(3), nullptr, L2b, N2);
    CONV(32, 1, 32, M_BLOCK, L2b, nullptr, nbr2, W32 + 3 * W32S, b32(4), nullptr, L2a, N2);   // x2
    CONV(32, 1, 64, M_BLOCK, L2a, nullptr, nbrd3, Wd3, b64(0), nullptr, L3a, N3);
    CONV(64, 1, 64, M_BLOCK, L3a, nullptr, nbr3, W64 + 0 * W64S, b64(1), nullptr, L3b, N3);
    CONV(64, 1, 64, M_BLOCK, L3b, nullptr, nbr3, W64 + 1 * W64S, b64(2), nullptr, L3a, N3);   // x3
    CONV(64, 1, 64, M_BLOCK, L3a, nullptr, nbrd4, W64 + 2 * W64S, b64(3), nullptr, L4a, N4);
    CONV(64, 1, 64, M_BLOCK, L4a, nullptr, nbr4, W64 + 3 * W64S, b64(4), nullptr, L4b, N4);
    CONV(64, 1, 64, M_BLOCK, L4b, nullptr, nbr4, W64 + 4 * W64S, b64(5), nullptr, L4a, N4);   // x4

    // ---- Bottom: basic(x4) + concat conv + reduce ----
    CONV(64, 1, 64, M_BLOCK, L4a, nullptr, nbr4, W64 + 5 * W64S, b64(6), nullptr, L4b, N4);
    CONV(64, 1, 64, M_RES, L4b, nullptr, nbr4, W64 + 6 * W64S, b64(7), L4a, L4c, N4);         // t
    CONV(64, 2, 64, M_RED, L4a, L4c, nbr4, W12864 + 0 * W12864S, b64(11), nullptr, L4b, N4);  // x

    // ---- Decoder level 3 ----
    CONV(64, 1, 64, M_BLOCK, L4b, nullptr, nbri4, W64 + 7 * W64S, b64(8), nullptr, L3b, N3);  // xu4
    CONV(64, 1, 64, M_BLOCK, L3a, nullptr, nbr3, W64 + 8 * W64S, b64(9), nullptr, L3c, N3);
    CONV(64, 1, 64, M_RES, L3c, nullptr, nbr3, W64 + 9 * W64S, b64(10), L3a, L3d, N3);        // t
    CONV(64, 2, 64, M_RED, L3b, L3d, nbr3, W12864 + 1 * W12864S, b64(12), nullptr, L3c, N3);  // x

    // ---- Decoder level 2 ----
    CONV(64, 1, 32, M_BLOCK, L3c, nullptr, nbri3, W6432 + 0 * W6432S, b32(11), nullptr, L2b, N2); // xu3
    CONV(32, 1, 32, M_BLOCK, L2a, nullptr, nbr2, W32 + 4 * W32S, b32(5), nullptr, L2c, N2);
    CONV(32, 1, 32, M_RES, L2c, nullptr, nbr2, W32 + 5 * W32S, b32(6), L2a, L2d, N2);             // t
    CONV(32, 2, 32, M_RED, L2b, L2d, nbr2, W6432 + 1 * W6432S, b32(12), nullptr, L2c, N2);        // x

    // ---- Decoder level 1 ----
    CONV(32, 1, 32, M_BLOCK, L2c, nullptr, nbri2, W32 + 6 * W32S, b32(7), nullptr, L1c, N1);  // xu2
    CONV(32, 1, 32, M_BLOCK, L1b, nullptr, nbr1, W32 + 7 * W32S, b32(8), nullptr, L1d, N1);
    CONV(32, 1, 32, M_RES, L1d, nullptr, nbr1, W32 + 8 * W32S, b32(9), L1b, L1e, N1);         // t
    CONV(32, 2, 32, M_RED, L1c, L1e, nbr1, W6432 + 2 * W6432S, b32(13), nullptr, L1d, N1);    // x

    // ---- Output ----
    CONV(32, 1, 32, M_BLOCK, L1d, nullptr, nbr1, W32 + 9 * W32S, b32(10), nullptr,
         (float*)d_out, N1);
}

// round 6
// speedup vs baseline: 2.7864x; 1.0324x over previous
#include <cuda_runtime.h>
#include <cuda_bf16.h>
#include <cstdint>

// ---------------------------------------------------------------------------
// Static scratch pool (no cudaMalloc allowed).
// ---------------------------------------------------------------------------
#define POOL_FLOATS 420000000LL
__device__ __align__(1024) float g_pool[POOL_FLOATS];

enum { M_BLOCK = 0, M_RES = 1, M_RED = 2 };

// ---------------------------------------------------------------------------
// Baseline-PTX helpers (compute_103: ldmatrix + mma.sync + cp.async only;
// tcgen05 is arch-accelerated and NOT available under this harness target).
// ---------------------------------------------------------------------------
static __device__ __forceinline__ uint32_t smem_u32_of(const void* p) {
    uint32_t a;
    asm("{ .reg .u64 t; cvta.to.shared.u64 t, %1; cvt.u32.u64 %0, t; }" : "=r"(a) : "l"(p));
    return a;
}
static __device__ __forceinline__ void ldm_x4(uint32_t* r, uint32_t addr) {
    asm volatile("ldmatrix.sync.aligned.m8n8.x4.shared.b16 {%0,%1,%2,%3}, [%4];"
                 : "=r"(r[0]), "=r"(r[1]), "=r"(r[2]), "=r"(r[3]) : "r"(addr));
}
static __device__ __forceinline__ void ldm_x2(uint32_t* r, uint32_t addr) {
    asm volatile("ldmatrix.sync.aligned.m8n8.x2.shared.b16 {%0,%1}, [%2];"
                 : "=r"(r[0]), "=r"(r[1]) : "r"(addr));
}
// D[16x8] += A[16x16](bf16,row) * B[16x8](bf16,col)
static __device__ __forceinline__ void mma16816(float* c, const uint32_t* a, const uint32_t* b) {
    asm volatile(
        "mma.sync.aligned.m16n8k16.row.col.f32.bf16.bf16.f32 "
        "{%0,%1,%2,%3}, {%4,%5,%6,%7}, {%8,%9}, {%0,%1,%2,%3};"
        : "+f"(c[0]), "+f"(c[1]), "+f"(c[2]), "+f"(c[3])
        : "r"(a[0]), "r"(a[1]), "r"(a[2]), "r"(a[3]), "r"(b[0]), "r"(b[1]));
}
// Split (x,y) into packed bf16x2 hi and lo (residual) words. Element 0 low 16.
static __device__ __forceinline__ void split2(float x, float y, uint32_t& hi, uint32_t& lo) {
    asm("cvt.rn.bf16x2.f32 %0, %1, %2;" : "=r"(hi) : "f"(y), "f"(x));
    float hx = __uint_as_float(hi << 16);
    float hy = __uint_as_float(hi & 0xffff0000u);
    asm("cvt.rn.bf16x2.f32 %0, %1, %2;" : "=r"(lo) : "f"(y - hy), "f"(x - hx));
}
static __device__ __forceinline__ void cp16(uint32_t dst, const void* src, uint32_t sz) {
    asm volatile("cp.async.ca.shared.global [%0], [%1], 16, %2;"
                 :: "r"(dst), "l"(src), "r"(sz) : "memory");
}
static __device__ __forceinline__ void cp8(uint32_t dst, const void* src, uint32_t sz) {
    asm volatile("cp.async.ca.shared.global [%0], [%1], 8, %2;"
                 :: "r"(dst), "l"(src), "r"(sz) : "memory");
}
static __device__ __forceinline__ void cp_commit() {
    asm volatile("cp.async.commit_group;" ::: "memory");
}
template<int W>
static __device__ __forceinline__ void cp_wait() {
    asm volatile("cp.async.wait_group %0;" :: "n"(W) : "memory");
}

// ---------------------------------------------------------------------------
// Convert f32 features -> bf16 hi/lo pairs: dst row r = [hi(C) | lo(C)].
// ---------------------------------------------------------------------------
__global__ void cvt_feat_kernel(const float* __restrict__ src, __nv_bfloat16* __restrict__ dst,
                                int N, int C) {
    int t = blockIdx.x * blockDim.x + threadIdx.x;
    if (t >= N * C) return;
    int r = t / C, c = t - r * C;
    float v = src[t];
    __nv_bfloat16 h = __float2bfloat16(v);
    dst[(size_t)r * 2 * C + c] = h;
    dst[(size_t)r * 2 * C + C + c] = __float2bfloat16(v - __bfloat162float(h));
}

// ---------------------------------------------------------------------------
// Weight prep: W[27][CINtot][COUT] f32 slice -> smem tile image per (k,chunk):
//   [k][ch][sel(hi/lo)][COUT][STR] bf16,  value = W[cin_off + ch*CPAD + c][n]
// ---------------------------------------------------------------------------
__global__ void prep_w_kernel(const float* __restrict__ Wsrc, __nv_bfloat16* __restrict__ dst,
                              int CIN, int CINtot, int cin_off, int COUT,
                              int NCH, int CPAD, int STR) {
    int t = blockIdx.x * blockDim.x + threadIdx.x;
    if (t >= 27 * COUT) return;
    int k = t / COUT, n = t - k * COUT;
    for (int ch = 0; ch < NCH; ch++) {
        __nv_bfloat16* dh = dst + ((size_t)(k * NCH + ch) * 2) * COUT * STR + (size_t)n * STR;
        __nv_bfloat16* dl = dh + (size_t)COUT * STR;
        for (int c = 0; c < CPAD; c++) {
            int cg = ch * CPAD + c;
            float v = (cg < CIN) ? Wsrc[((size_t)k * CINtot + cin_off + cg) * COUT + n] : 0.0f;
            __nv_bfloat16 h = __float2bfloat16(v);
            dh[c] = h;
            dl[c] = __float2bfloat16(v - __bfloat162float(h));
        }
    }
}

// ---------------------------------------------------------------------------
// Sparse gather-conv: bf16 split precision (3 MMAs ~ fp32), cp.async
// double-buffered pipeline. CTA = 128 rows, 4 warps. Features stored as
// bf16 hi/lo pairs; K processed in 32-wide chunks.
// ---------------------------------------------------------------------------
template<int CIN, int NPHASE, int COUT, int MODE, bool OUTF32>
__global__ void __launch_bounds__(128)
conv_mma_kernel(const __nv_bfloat16* __restrict__ featA,
                const __nv_bfloat16* __restrict__ featB,
                const int* __restrict__ nbr,
                const __nv_bfloat16* __restrict__ Bw,
                const float* __restrict__ sb,
                const __nv_bfloat16* __restrict__ resbf,
                float* __restrict__ outf,
                __nv_bfloat16* __restrict__ outbf, int N) {
    constexpr int CPAD = (CIN >= 32) ? 32 : 16;
    constexpr int NCH = (CIN >= 32) ? CIN / 32 : 1;
    constexpr int KS = CPAD / 16;
    constexpr int STR = CPAD + 8;               // halves; row = 80B (or 48B) -> conflict-free
    constexpr int NT = COUT / 8;
    constexpr int IPK = NPHASE * NCH;
    constexpr int TOT = 27 * IPK;

    constexpr uint32_t A_HALF = 128u * STR * 2;  // bytes of one hi (or lo) A tile
    constexpr uint32_t ABUF = 2 * A_HALF;        // hi+lo
    constexpr uint32_t BBUF = 2u * COUT * STR * 2;
    constexpr uint32_t OFF_B = 2 * ABUF;
    constexpr uint32_t OFF_NBR = 2 * ABUF + 2 * BBUF;
    constexpr size_t PH_STRIDE = (size_t)27 * NCH * 2 * COUT * STR;

    extern __shared__ __align__(16) char smem[];
    const uint32_t sbase = smem_u32_of(smem);
    int* sNbr = (int*)(smem + OFF_NBR);

    const int tid = threadIdx.x;
    const int wid = tid >> 5;
    const int lane = tid & 31;
    const long long r0 = (long long)blockIdx.x * 128;

    // Stage neighbor table (coalesced); zero A buffers if K padded (CIN=4).
    const long long NI = (long long)N * 27;
    for (int i = tid; i < 128 * 27; i += 128) {
        long long g = r0 * 27 + i;
        sNbr[i] = (g < NI) ? nbr[g] : -1;
    }
    if constexpr (CIN < 32) {
        for (int i = tid; i < (int)(2 * ABUF / 16); i += 128)
            ((float4*)smem)[i] = make_float4(0.f, 0.f, 0.f, 0.f);
    }
    __syncthreads();

    auto issue = [&](int it) {
        const int k = it / IPK;
        const int rem = it - k * IPK;
        const int ph = (NPHASE > 1) ? rem / NCH : 0;
        const int ch = (NPHASE > 1) ? rem - ph * NCH : rem;
        const uint32_t b = (uint32_t)(it & 1);
        // A gather: thread t owns row t. Row image: [hi(CIN) | lo(CIN)] bf16.
        {
            const __nv_bfloat16* f = (NPHASE > 1 && ph) ? featB : featA;
            const int idx = sNbr[tid * 27 + k];
            const uint32_t dh = sbase + b * ABUF + (uint32_t)tid * STR * 2;
            const uint32_t dl = dh + A_HALF;
            if constexpr (CIN >= 32) {
                const uint32_t sz = (idx >= 0) ? 16u : 0u;
                const size_t base = (size_t)(idx >= 0 ? idx : 0) * 2 * CIN + (size_t)ch * 32;
                const __nv_bfloat16* sh_ = f + base;
                const __nv_bfloat16* sl_ = f + base + CIN;
#pragma unroll
                for (int u = 0; u < 4; u++) {
                    cp16(dh + u * 16, sh_ + u * 8, sz);
                    cp16(dl + u * 16, sl_ + u * 8, sz);
                }
            } else {
                const uint32_t sz = (idx >= 0) ? 8u : 0u;
                const __nv_bfloat16* s_ = f + (size_t)(idx >= 0 ? idx : 0) * 8;
                cp8(dh, s_, sz);
                cp8(dl, s_ + 4, sz);
            }
        }
        // B stage: linear copy of the pre-baked tile image.
        {
            const __nv_bfloat16* bs = Bw + ((NPHASE > 1) ? (size_t)ph * PH_STRIDE : 0) +
                                      (size_t)((k * NCH + ch) * 2) * COUT * STR;
            constexpr int NU = (int)(BBUF / 16);
            const uint32_t dst = sbase + OFF_B + b * BBUF;
            for (int i = tid; i < NU; i += 128) cp16(dst + i * 16, bs + i * 8, 16u);
        }
        cp_commit();
    };

    float acc[2][NT][4];
#pragma unroll
    for (int rt = 0; rt < 2; rt++)
#pragma unroll
        for (int j = 0; j < NT; j++)
#pragma unroll
            for (int u = 0; u < 4; u++) acc[rt][j][u] = 0.0f;

    issue(0);
    for (int it = 0; it < TOT; ++it) {
        if (it + 1 < TOT) {
            issue(it + 1);
            cp_wait<1>();
        } else {
            cp_wait<0>();
        }
        __syncthreads();

        const uint32_t b = (uint32_t)(it & 1);
        const uint32_t abase = sbase + b * ABUF;
        const uint32_t bbase = sbase + OFF_B + b * BBUF;
        const uint32_t rowbase = (uint32_t)wid * 32;
#pragma unroll
        for (int s = 0; s < KS; s++) {
            uint32_t ahi[2][4], alo[2][4];
#pragma unroll
            for (int rt = 0; rt < 2; rt++) {
                const uint32_t arow = rowbase + rt * 16 + (lane & 15);
                const uint32_t acol = (uint32_t)s * 16 + (((uint32_t)lane >> 4) << 3);
                const uint32_t aoff = (arow * STR + acol) * 2;
                ldm_x4(ahi[rt], abase + aoff);
                ldm_x4(alo[rt], abase + A_HALF + aoff);
            }
#pragma unroll
            for (int j = 0; j < NT; j++) {
                const uint32_t brow = (uint32_t)j * 8 + (lane & 7);
                const uint32_t bcol = (uint32_t)s * 16 + ((lane & 8) ? 8u : 0u);
                const uint32_t boff = (brow * STR + bcol) * 2;
                uint32_t bhi[2], blo[2];
                ldm_x2(bhi, bbase + boff);
                ldm_x2(blo, bbase + (uint32_t)COUT * STR * 2 + boff);
#pragma unroll
                for (int rt = 0; rt < 2; rt++) {
                    mma16816(acc[rt][j], ahi[rt], bhi);
                    mma16816(acc[rt][j], ahi[rt], blo);
                    mma16816(acc[rt][j], alo[rt], bhi);
                }
            }
        }
        __syncthreads();
    }

    // Epilogue. Fragment (rt,j): c0,c1 -> row wid*32+rt*16+lane/4, cols n0,n0+1;
    // c2,c3 -> row +8.
    const float* scale = sb;
    const float* bias = sb + COUT;
#pragma unroll
    for (int j = 0; j < NT; j++) {
        const int n0 = j * 8 + 2 * (lane & 3);
        const float sc0 = scale[n0], sc1 = scale[n0 + 1];
        const float bi0 = bias[n0], bi1 = bias[n0 + 1];
#pragma unroll
        for (int rt = 0; rt < 2; rt++)
#pragma unroll
            for (int h = 0; h < 2; h++) {
                const long long r = r0 + wid * 32 + rt * 16 + (lane >> 2) + h * 8;
                if (r >= N) continue;
                float v0 = acc[rt][j][2 * h + 0] * sc0 + bi0;
                float v1 = acc[rt][j][2 * h + 1] * sc1 + bi1;
                if constexpr (MODE == M_RES) {
                    const __nv_bfloat16* rb = resbf + (size_t)r * 2 * COUT;
                    __nv_bfloat162 rh = *(const __nv_bfloat162*)(rb + n0);
                    __nv_bfloat162 rl = *(const __nv_bfloat162*)(rb + COUT + n0);
                    v0 += __bfloat162float(rh.x) + __bfloat162float(rl.x);
                    v1 += __bfloat162float(rh.y) + __bfloat162float(rl.y);
                }
                v0 = fmaxf(v0, 0.0f);
                v1 = fmaxf(v1, 0.0f);
                if constexpr (MODE == M_RED) {
#pragma unroll
                    for (int u = 0; u < 2; u++) {
                        const int c = n0 + u;
                        const __nv_bfloat16* src;
                        int cc;
                        if (2 * c + 1 < CIN) { src = featA + (size_t)r * 2 * CIN; cc = 2 * c; }
                        else { src = featB + (size_t)r * 2 * CIN; cc = 2 * c - CIN; }
                        __nv_bfloat162 hh = *(const __nv_bfloat162*)(src + cc);
                        __nv_bfloat162 ll = *(const __nv_bfloat162*)(src + CIN + cc);
                        float rsum = __bfloat162float(hh.x) + __bfloat162float(ll.x) +
                                     __bfloat162float(hh.y) + __bfloat162float(ll.y);
                        if (u == 0) v0 += rsum; else v1 += rsum;
                    }
                }
                if constexpr (OUTF32) {
                    *(float2*)(outf + (size_t)r * COUT + n0) = make_float2(v0, v1);
                } else {
                    uint32_t hw, lw;
                    split2(v0, v1, hw, lw);
                    *(uint32_t*)(outbf + (size_t)r * 2 * COUT + n0) = hw;
                    *(uint32_t*)(outbf + (size_t)r * 2 * COUT + COUT + n0) = lw;
                }
            }
    }
}

// ---------------------------------------------------------------------------
// Host orchestration
// ---------------------------------------------------------------------------
#define CONV(CIN_, NPH_, CO_, MO_, OUTF_, fa, fb, nb, Wsrc, sbp, rs, outf_, outbf_, n)        \
    do {                                                                                      \
        constexpr int CPAD_ = ((CIN_) >= 32) ? 32 : 16;                                       \
        constexpr int NCH_ = ((CIN_) >= 32) ? (CIN_) / 32 : 1;                                \
        constexpr int STR_ = CPAD_ + 8;                                                       \
        __nv_bfloat16* bw = bfalloc((size_t)(NPH_) * 27 * NCH_ * 2 * (CO_) * STR_);           \
        for (int ph = 0; ph < (NPH_); ph++)                                                   \
            prep_w_kernel<<<(27 * (CO_) + 127) / 128, 128>>>(                                 \
                Wsrc, bw + (size_t)ph * 27 * NCH_ * 2 * (CO_) * STR_, CIN_, (CIN_) * (NPH_),  \
                ph * (CIN_), CO_, NCH_, CPAD_, STR_);                                         \
        auto kfn = conv_mma_kernel<CIN_, NPH_, CO_, MO_, OUTF_>;                              \
        constexpr size_t sh = (size_t)2 * (2 * 128 * STR_ * 2) +                              \
                              (size_t)2 * (2 * (CO_) * STR_ * 2) + (size_t)128 * 27 * 4;      \
        cudaFuncSetAttribute(kfn, cudaFuncAttributeMaxDynamicSharedMemorySize, (int)sh);      \
        kfn<<<(unsigned)(((n) + 127) / 128), 128, sh>>>(fa, fb, nb, bw, sbp, rs, outf_,       \
                                                        outbf_, n);                          \
    } while (0)

extern "C" void kernel_launch(void* const* d_in, const int* in_sizes, int n_in,
                              void* d_out, int out_size) {
    (void)n_in; (void)out_size;
    const float* vf     = (const float*)d_in[0];
    const float* Win    = (const float*)d_in[1];
    const float* W32    = (const float*)d_in[2];
    const float* W64    = (const float*)d_in[3];
    const float* Wd3    = (const float*)d_in[4];
    const float* W6432  = (const float*)d_in[5];
    const float* W12864 = (const float*)d_in[6];
    const float* bn32   = (const float*)d_in[7];
    const float* bn64   = (const float*)d_in[8];
    const int* nbr1  = (const int*)d_in[9];
    const int* nbr2  = (const int*)d_in[10];
    const int* nbr3  = (const int*)d_in[11];
    const int* nbr4  = (const int*)d_in[12];
    const int* nbrd2 = (const int*)d_in[13];
    const int* nbrd3 = (const int*)d_in[14];
    const int* nbrd4 = (const int*)d_in[15];
    const int* nbri4 = (const int*)d_in[16];
    const int* nbri3 = (const int*)d_in[17];
    const int* nbri2 = (const int*)d_in[18];

    const int N1 = in_sizes[9]  / 27;
    const int N2 = in_sizes[10] / 27;
    const int N3 = in_sizes[11] / 27;
    const int N4 = in_sizes[12] / 27;

    float* pool = nullptr;
    cudaGetSymbolAddress((void**)&pool, g_pool);
    size_t off = 0;
    auto alloc = [&](size_t nfloats) {
        float* p = pool + off;
        off += (nfloats + 255) & ~(size_t)255;  // keep 1KB alignment
        return p;
    };
    auto bfalloc = [&](size_t nbf) { return (__nv_bfloat16*)alloc((nbf + 1) / 2); };

    // Input features -> bf16 hi/lo
    __nv_bfloat16* VF = bfalloc((size_t)N1 * 8);
    cvt_feat_kernel<<<(N1 * 4 + 255) / 256, 256>>>(vf, VF, N1, 4);

    // Feature buffers (bf16 hi/lo pairs: N * 2*C halves)
    __nv_bfloat16* L1a = bfalloc((size_t)N1 * 64);
    __nv_bfloat16* L1b = bfalloc((size_t)N1 * 64);
    __nv_bfloat16* L1c = bfalloc((size_t)N1 * 64);
    __nv_bfloat16* L1d = bfalloc((size_t)N1 * 64);
    __nv_bfloat16* L1e = bfalloc((size_t)N1 * 64);
    __nv_bfloat16* L2a = bfalloc((size_t)N2 * 64);
    __nv_bfloat16* L2b = bfalloc((size_t)N2 * 64);
    __nv_bfloat16* L2c = bfalloc((size_t)N2 * 64);
    __nv_bfloat16* L2d = bfalloc((size_t)N2 * 64);
    __nv_bfloat16* L3a = bfalloc((size_t)N3 * 128);
    __nv_bfloat16* L3b = bfalloc((size_t)N3 * 128);
    __nv_bfloat16* L3c = bfalloc((size_t)N3 * 128);
    __nv_bfloat16* L3d = bfalloc((size_t)N3 * 128);
    __nv_bfloat16* L4a = bfalloc((size_t)N4 * 128);
    __nv_bfloat16* L4b = bfalloc((size_t)N4 * 128);
    __nv_bfloat16* L4c = bfalloc((size_t)N4 * 128);

    const long long W32S = 27LL * 32 * 32;
    const long long W64S = 27LL * 64 * 64;
    const long long W6432S = 27LL * 64 * 32;
    const long long W12864S = 27LL * 128 * 64;
    auto b32 = [&](int j) { return bn32 + (long long)j * 64; };
    auto b64 = [&](int j) { return bn64 + (long long)j * 128; };
    float* nof = nullptr;
    __nv_bfloat16* nob = nullptr;

    // ---- Encoder ----
    CONV(4, 1, 32, M_BLOCK, false, VF, nob, nbr1, Win, b32(0), nob, nof, L1a, N1);
    CONV(32, 1, 32, M_BLOCK, false, L1a, nob, nbr1, W32 + 0 * W32S, b32(1), nob, nof, L1b, N1);   // x1
    CONV(32, 1, 32, M_BLOCK, false, L1b, nob, nbrd2, W32 + 1 * W32S, b32(2), nob, nof, L2a, N2);
    CONV(32, 1, 32, M_BLOCK, false, L2a, nob, nbr2, W32 + 2 * W32S, b32(3), nob, nof, L2b, N2);
    CONV(32, 1, 32, M_BLOCK, false, L2b, nob, nbr2, W32 + 3 * W32S, b32(4), nob, nof, L2a, N2);   // x2
    CONV(32, 1, 64, M_BLOCK, false, L2a, nob, nbrd3, Wd3, b64(0), nob, nof, L3a, N3);
    CONV(64, 1, 64, M_BLOCK, false, L3a, nob, nbr3, W64 + 0 * W64S, b64(1), nob, nof, L3b, N3);
    CONV(64, 1, 64, M_BLOCK, false, L3b, nob, nbr3, W64 + 1 * W64S, b64(2), nob, nof, L3a, N3);   // x3
    CONV(64, 1, 64, M_BLOCK, false, L3a, nob, nbrd4, W64 + 2 * W64S, b64(3), nob, nof, L4a, N4);
    CONV(64, 1, 64, M_BLOCK, false, L4a, nob, nbr4, W64 + 3 * W64S, b64(4), nob, nof, L4b, N4);
    CONV(64, 1, 64, M_BLOCK, false, L4b, nob, nbr4, W64 + 4 * W64S, b64(5), nob, nof, L4a, N4);   // x4

    // ---- Bottom: basic(x4) + concat conv + reduce ----
    CONV(64, 1, 64, M_BLOCK, false, L4a, nob, nbr4, W64 + 5 * W64S, b64(6), nob, nof, L4b, N4);
    CONV(64, 1, 64, M_RES, false, L4b, nob, nbr4, W64 + 6 * W64S, b64(7), L4a, nof, L4c, N4);     // t
    CONV(64, 2, 64, M_RED, false, L4a, L4c, nbr4, W12864 + 0 * W12864S, b64(11), nob, nof, L4b, N4);

    // ---- Decoder level 3 ----
    CONV(64, 1, 64, M_BLOCK, false, L4b, nob, nbri4, W64 + 7 * W64S, b64(8), nob, nof, L3b, N3);  // xu4
    CONV(64, 1, 64, M_BLOCK, false, L3a, nob, nbr3, W64 + 8 * W64S, b64(9), nob, nof, L3c, N3);
    CONV(64, 1, 64, M_RES, false, L3c, nob, nbr3, W64 + 9 * W64S, b64(10), L3a, nof, L3d, N3);    // t
    CONV(64, 2, 64, M_RED, false, L3b, L3d, nbr3, W12864 + 1 * W12864S, b64(12), nob, nof, L3c, N3);

    // ---- Decoder level 2 ----
    CONV(64, 1, 32, M_BLOCK, false, L3c, nob, nbri3, W6432 + 0 * W6432S, b32(11), nob, nof, L2b, N2); // xu3
    CONV(32, 1, 32, M_BLOCK, false, L2a, nob, nbr2, W32 + 4 * W32S, b32(5), nob, nof, L2c, N2);
    CONV(32, 1, 32, M_RES, false, L2c, nob, nbr2, W32 + 5 * W32S, b32(6), L2a, nof, L2d, N2);         // t
    CONV(32, 2, 32, M_RED, false, L2b, L2d, nbr2, W6432 + 1 * W6432S, b32(12), nob, nof, L2c, N2);

    // ---- Decoder level 1 ----
    CONV(32, 1, 32, M_BLOCK, false, L2c, nob, nbri2, W32 + 6 * W32S, b32(7), nob, nof, L1c, N1);  // xu2
    CONV(32, 1, 32, M_BLOCK, false, L1b, nob, nbr1, W32 + 7 * W32S, b32(8), nob, nof, L1d, N1);
    CONV(32, 1, 32, M_RES, false, L1d, nob, nbr1, W32 + 8 * W32S, b32(9), L1b, nof, L1e, N1);     // t
    CONV(32, 2, 32, M_RED, false, L1c, L1e, nbr1, W6432 + 2 * W6432S, b32(13), nob, nof, L1d, N1);

    // ---- Output (f32) ----
    CONV(32, 1, 32, M_BLOCK, true, L1d, nob, nbr1, W32 + 9 * W32S, b32(10), nob,
         (float*)d_out, nob, N1);
}

// round 13
// speedup vs baseline: 4.1383x; 1.4852x over previous
#include <cuda_runtime.h>
#include <cuda_bf16.h>
#include <cstdint>

// ---------------------------------------------------------------------------
// Static scratch pool (no cudaMalloc allowed).
// ---------------------------------------------------------------------------
#define POOL_FLOATS 420000000LL
__device__ __align__(1024) float g_pool[POOL_FLOATS];

enum { M_BLOCK = 0, M_RES = 1, M_RED = 2 };

// ---------------------------------------------------------------------------
// Baseline-PTX helpers (compute_103: ldmatrix + mma.sync + cp.async only;
// tcgen05 is arch-accelerated and NOT available under this harness target).
// ---------------------------------------------------------------------------
static __device__ __forceinline__ uint32_t smem_u32_of(const void* p) {
    uint32_t a;
    asm("{ .reg .u64 t; cvta.to.shared.u64 t, %1; cvt.u32.u64 %0, t; }" : "=r"(a) : "l"(p));
    return a;
}
static __device__ __forceinline__ void ldm_x4(uint32_t* r, uint32_t addr) {
    asm volatile("ldmatrix.sync.aligned.m8n8.x4.shared.b16 {%0,%1,%2,%3}, [%4];"
                 : "=r"(r[0]), "=r"(r[1]), "=r"(r[2]), "=r"(r[3]) : "r"(addr));
}
// D[16x8] += A[16x16](bf16,row) * B[16x8](bf16,col)
static __device__ __forceinline__ void mma16816(float* c, const uint32_t* a, const uint32_t* b) {
    asm volatile(
        "mma.sync.aligned.m16n8k16.row.col.f32.bf16.bf16.f32 "
        "{%0,%1,%2,%3}, {%4,%5,%6,%7}, {%8,%9}, {%0,%1,%2,%3};"
        : "+f"(c[0]), "+f"(c[1]), "+f"(c[2]), "+f"(c[3])
        : "r"(a[0]), "r"(a[1]), "r"(a[2]), "r"(a[3]), "r"(b[0]), "r"(b[1]));
}
// Split (x,y) into packed bf16x2 hi and lo (residual) words. Element 0 low 16.
static __device__ __forceinline__ void split2(float x, float y, uint32_t& hi, uint32_t& lo) {
    asm("cvt.rn.bf16x2.f32 %0, %1, %2;" : "=r"(hi) : "f"(y), "f"(x));
    float hx = __uint_as_float(hi << 16);
    float hy = __uint_as_float(hi & 0xffff0000u);
    asm("cvt.rn.bf16x2.f32 %0, %1, %2;" : "=r"(lo) : "f"(y - hy), "f"(x - hx));
}
static __device__ __forceinline__ void cp16(uint32_t dst, const void* src, uint32_t sz) {
    asm volatile("cp.async.ca.shared.global [%0], [%1], 16, %2;"
                 :: "r"(dst), "l"(src), "r"(sz) : "memory");
}
static __device__ __forceinline__ void cp8(uint32_t dst, const void* src, uint32_t sz) {
    asm volatile("cp.async.ca.shared.global [%0], [%1], 8, %2;"
                 :: "r"(dst), "l"(src), "r"(sz) : "memory");
}
static __device__ __forceinline__ void cp_commit() {
    asm volatile("cp.async.commit_group;" ::: "memory");
}
template<int W>
static __device__ __forceinline__ void cp_wait() {
    asm volatile("cp.async.wait_group %0;" :: "n"(W) : "memory");
}

// ---------------------------------------------------------------------------
// Convert f32 features -> bf16 hi/lo pairs: dst row r = [hi(C) | lo(C)].
// ---------------------------------------------------------------------------
__global__ void cvt_feat_kernel(const float* __restrict__ src, __nv_bfloat16* __restrict__ dst,
                                int N, int C) {
    int t = blockIdx.x * blockDim.x + threadIdx.x;
    if (t >= N * C) return;
    int r = t / C, c = t - r * C;
    float v = src[t];
    __nv_bfloat16 h = __float2bfloat16(v);
    dst[(size_t)r * 2 * C + c] = h;
    dst[(size_t)r * 2 * C + C + c] = __float2bfloat16(v - __bfloat162float(h));
}

// ---------------------------------------------------------------------------
// Batched weight prep: all conv weights -> mma B-fragment order, one launch.
// Entry element order: [k][ch][j][s][sel(hi/lo)][lane], each element one
// uint2 = {b0, b1} for mma.m16n8k16 (B col-major, thread 'lane').
//   b0 = pack(B[kk][n], B[kk+1][n]),  b1 = same rows +8
//   n = j*8 + lane/4,  kk = s*16 + (lane%4)*2,  B[c][n] = W[cinOff+ch*32+c][n]
// ---------------------------------------------------------------------------
struct Ent {
    const float* src;
    long long dstOff;   // uint2 units into frag pool
    long long nElem;
    int cin, cinTot, cinOff, cout, nch, ks;
};
struct Tbl {
    Ent e[40];
    int n;
};

__global__ void prep_all_kernel(Tbl tbl, uint2* __restrict__ pool) {
    const Ent E = tbl.e[blockIdx.y];
    const int NT = E.cout / 8;
    for (long long i = (long long)blockIdx.x * blockDim.x + threadIdx.x; i < E.nElem;
         i += (long long)gridDim.x * blockDim.x) {
        const int lane = (int)(i & 31);
        long long r = i >> 5;
        const int sel = (int)(r & 1); r >>= 1;
        const int s = (int)(r % E.ks); r /= E.ks;
        const int j = (int)(r % NT); r /= NT;
        const int ch = (int)(r % E.nch);
        const int k = (int)(r / E.nch);
        const int n = j * 8 + (lane >> 2);
        const int kk = s * 16 + (lane & 3) * 2;
        const int cb = ch * 32;
        auto val = [&](int c) -> float {
            int cg = cb + c;
            return (cg < E.cin)
                       ? E.src[((size_t)k * E.cinTot + E.cinOff + cg) * E.cout + n]
                       : 0.0f;
        };
        float a0 = val(kk), a1 = val(kk + 1), c0 = val(kk + 8), c1 = val(kk + 9);
        uint32_t h, l, w0, w1;
        split2(a0, a1, h, l);
        w0 = sel ? l : h;
        split2(c0, c1, h, l);
        w1 = sel ? l : h;
        pool[E.dstOff + i] = make_uint2(w0, w1);
    }
}

// ---------------------------------------------------------------------------
// Sparse gather-conv: bf16 split precision (3 MMAs ~ fp32).
// CTA = 128 rows, 4 warps; warp w owns rows 32w..32w+31 and thread t gathers
// row t => the mainloop needs NO CTA barriers (cp.async + __syncwarp only).
// B fragments come straight from gmem (L1-resident), A via smem ldmatrix.
// ---------------------------------------------------------------------------
template<int CIN, int NPHASE, int COUT, int MODE, bool OUTF32>
__global__ void __launch_bounds__(128, 4)
conv_mma_kernel(const __nv_bfloat16* __restrict__ featA,
                const __nv_bfloat16* __restrict__ featB,
                const int* __restrict__ nbr,
                const uint2* __restrict__ frag,
                const float* __restrict__ sb,
                const __nv_bfloat16* __restrict__ resbf,
                float* __restrict__ outf,
                __nv_bfloat16* __restrict__ outbf, int N) {
    constexpr int CPAD = (CIN >= 32) ? 32 : 16;
    constexpr int NCH = (CIN >= 32) ? CIN / 32 : 1;
    constexpr int KS = CPAD / 16;
    constexpr int STR = CPAD + 8;               // halves per smem A row
    constexpr int NT = COUT / 8;
    constexpr int IPK = NPHASE * NCH;
    constexpr int TOT = 27 * IPK;
    constexpr size_t FRAG_IT = (size_t)NT * KS * 2 * 32;   // uint2 per (k,ch)
    constexpr size_t PH_STRIDE = (size_t)27 * NCH * FRAG_IT;

    constexpr uint32_t A_HALF = 128u * STR * 2;  // one hi (or lo) A tile, bytes
    constexpr uint32_t ABUF = 2 * A_HALF;        // hi+lo
    constexpr uint32_t OFF_NBR = 2 * ABUF;

    extern __shared__ __align__(16) char smem[];
    const uint32_t sbase = smem_u32_of(smem);
    int* sNbr = (int*)(smem + OFF_NBR);

    const int tid = threadIdx.x;
    const int wid = tid >> 5;
    const int lane = tid & 31;
    const long long r0 = (long long)blockIdx.x * 128;

    // Stage neighbor table (coalesced); zero A buffers if K padded (CIN=4).
    const long long NI = (long long)N * 27;
    for (int i = tid; i < 128 * 27; i += 128) {
        long long g = r0 * 27 + i;
        sNbr[i] = (g < NI) ? nbr[g] : -1;
    }
    if constexpr (CIN < 32) {
        for (int i = tid; i < (int)(2 * ABUF / 16); i += 128)
            ((float4*)smem)[i] = make_float4(0.f, 0.f, 0.f, 0.f);
    }
    __syncthreads();  // only CTA barrier in the kernel

    auto issue = [&](int it) {
        const int k = it / IPK;
        const int rem = it - k * IPK;
        const int ph = (NPHASE > 1) ? rem / NCH : 0;
        const int ch = (NPHASE > 1) ? rem - ph * NCH : rem;
        const uint32_t b = (uint32_t)(it & 1);
        const __nv_bfloat16* f = (NPHASE > 1 && ph) ? featB : featA;
        const int idx = sNbr[tid * 27 + k];
        const uint32_t dh = sbase + b * ABUF + (uint32_t)tid * STR * 2;
        const uint32_t dl = dh + A_HALF;
        if constexpr (CIN >= 32) {
            const uint32_t sz = (idx >= 0) ? 16u : 0u;
            const size_t base = (size_t)(idx >= 0 ? idx : 0) * 2 * CIN + (size_t)ch * 32;
            const __nv_bfloat16* sh_ = f + base;
            const __nv_bfloat16* sl_ = f + base + CIN;
#pragma unroll
            for (int u = 0; u < 4; u++) {
                cp16(dh + u * 16, sh_ + u * 8, sz);
                cp16(dl + u * 16, sl_ + u * 8, sz);
            }
        } else {
            const uint32_t sz = (idx >= 0) ? 8u : 0u;
            const __nv_bfloat16* s_ = f + (size_t)(idx >= 0 ? idx : 0) * 8;
            cp8(dh, s_, sz);
            cp8(dl, s_ + 4, sz);
        }
        cp_commit();
    };

    float acc[2][NT][4];
#pragma unroll
    for (int rt = 0; rt < 2; rt++)
#pragma unroll
        for (int j = 0; j < NT; j++)
#pragma unroll
            for (int u = 0; u < 4; u++) acc[rt][j][u] = 0.0f;

    issue(0);
    for (int it = 0; it < TOT; ++it) {
        const int k = it / IPK;
        const int rem = it - k * IPK;
        const int ph = (NPHASE > 1) ? rem / NCH : 0;
        const int ch = (NPHASE > 1) ? rem - ph * NCH : rem;
        if (it + 1 < TOT) {
            issue(it + 1);
            cp_wait<1>();
        } else {
            cp_wait<0>();
        }
        __syncwarp();  // warp-wide visibility of this warp's gathered rows

        const uint2* fb = frag + ((NPHASE > 1) ? (size_t)ph * PH_STRIDE : 0) +
                          (size_t)(k * NCH + ch) * FRAG_IT;
        const uint32_t abase = sbase + (uint32_t)(it & 1) * ABUF;
        const uint32_t rowbase = (uint32_t)wid * 32;
#pragma unroll
        for (int s = 0; s < KS; s++) {
            uint32_t ahi[2][4], alo[2][4];
#pragma unroll
            for (int rt = 0; rt < 2; rt++) {
                const uint32_t arow = rowbase + rt * 16 + (lane & 15);
                const uint32_t acol = (uint32_t)s * 16 + (((uint32_t)lane >> 4) << 3);
                const uint32_t aoff = (arow * STR + acol) * 2;
                ldm_x4(ahi[rt], abase + aoff);
                ldm_x4(alo[rt], abase + A_HALF + aoff);
            }
#pragma unroll
            for (int j = 0; j < NT; j++) {
                const uint2 bh = __ldg(fb + ((size_t)(j * KS + s) * 2 + 0) * 32 + lane);
                const uint2 bl = __ldg(fb + ((size_t)(j * KS + s) * 2 + 1) * 32 + lane);
                const uint32_t bhi[2] = {bh.x, bh.y};
                const uint32_t blo[2] = {bl.x, bl.y};
#pragma unroll
                for (int rt = 0; rt < 2; rt++) {
                    mma16816(acc[rt][j], ahi[rt], bhi);
                    mma16816(acc[rt][j], ahi[rt], blo);
                    mma16816(acc[rt][j], alo[rt], bhi);
                }
            }
        }
        __syncwarp();  // all lanes done reading buffer before it is re-filled
    }

    // Epilogue. Fragment (rt,j): c0,c1 -> row wid*32+rt*16+lane/4, cols n0,n0+1;
    // c2,c3 -> row +8.
    const float* scale = sb;
    const float* bias = sb + COUT;
#pragma unroll
    for (int j = 0; j < NT; j++) {
        const int n0 = j * 8 + 2 * (lane & 3);
        const float sc0 = scale[n0], sc1 = scale[n0 + 1];
        const float bi0 = bias[n0], bi1 = bias[n0 + 1];
#pragma unroll
        for (int rt = 0; rt < 2; rt++)
#pragma unroll
            for (int h = 0; h < 2; h++) {
                const long long r = r0 + wid * 32 + rt * 16 + (lane >> 2) + h * 8;
                if (r >= N) continue;
                float v0 = acc[rt][j][2 * h + 0] * sc0 + bi0;
                float v1 = acc[rt][j][2 * h + 1] * sc1 + bi1;
                if constexpr (MODE == M_RES) {
                    const __nv_bfloat16* rb = resbf + (size_t)r * 2 * COUT;
                    __nv_bfloat162 rh = *(const __nv_bfloat162*)(rb + n0);
                    __nv_bfloat162 rl = *(const __nv_bfloat162*)(rb + COUT + n0);
                    v0 += __bfloat162float(rh.x) + __bfloat162float(rl.x);
                    v1 += __bfloat162float(rh.y) + __bfloat162float(rl.y);
                }
                v0 = fmaxf(v0, 0.0f);
                v1 = fmaxf(v1, 0.0f);
                if constexpr (MODE == M_RED) {
#pragma unroll
                    for (int u = 0; u < 2; u++) {
                        const int c = n0 + u;
                        const __nv_bfloat16* src;
                        int cc;
                        if (2 * c + 1 < CIN) { src = featA + (size_t)r * 2 * CIN; cc = 2 * c; }
                        else { src = featB + (size_t)r * 2 * CIN; cc = 2 * c - CIN; }
                        __nv_bfloat162 hh = *(const __nv_bfloat162*)(src + cc);
                        __nv_bfloat162 ll = *(const __nv_bfloat162*)(src + CIN + cc);
                        float rsum = __bfloat162float(hh.x) + __bfloat162float(ll.x) +
                                     __bfloat162float(hh.y) + __bfloat162float(ll.y);
                        if (u == 0) v0 += rsum; else v1 += rsum;
                    }
                }
                if constexpr (OUTF32) {
                    *(float2*)(outf + (size_t)r * COUT + n0) = make_float2(v0, v1);
                } else {
                    uint32_t hw, lw;
                    split2(v0, v1, hw, lw);
                    *(uint32_t*)(outbf + (size_t)r * 2 * COUT + n0) = hw;
                    *(uint32_t*)(outbf + (size_t)r * 2 * COUT + COUT + n0) = lw;
                }
            }
    }
}

// ---------------------------------------------------------------------------
// Host orchestration
// ---------------------------------------------------------------------------
#define CONV(CIN_, NPH_, CO_, MO_, OUTF_, fa, fb, nb, fragoff, sbp, rs, outf_, outbf_, n)     \
    do {                                                                                      \
        constexpr int STR_ = (((CIN_) >= 32) ? 32 : 16) + 8;                                  \
        auto kfn = conv_mma_kernel<CIN_, NPH_, CO_, MO_, OUTF_>;                              \
        constexpr size_t sh = (size_t)2 * (2 * 128 * STR_ * 2) + (size_t)128 * 27 * 4;        \
        cudaFuncSetAttribute(kfn, cudaFuncAttributeMaxDynamicSharedMemorySize, (int)sh);      \
        kfn<<<(unsigned)(((n) + 127) / 128), 128, sh>>>(fa, fb, nb, fragPool + (fragoff),     \
                                                        sbp, rs, outf_, outbf_, n);           \
    } while (0)

extern "C" void kernel_launch(void* const* d_in, const int* in_sizes, int n_in,
                              void* d_out, int out_size) {
    (void)n_in; (void)out_size;
    const float* vf     = (const float*)d_in[0];
    const float* Win    = (const float*)d_in[1];
    const float* W32    = (const float*)d_in[2];
    const float* W64    = (const float*)d_in[3];
    const float* Wd3    = (const float*)d_in[4];
    const float* W6432  = (const float*)d_in[5];
    const float* W12864 = (const float*)d_in[6];
    const float* bn32   = (const float*)d_in[7];
    const float* bn64   = (const float*)d_in[8];
    const int* nbr1  = (const int*)d_in[9];
    const int* nbr2  = (const int*)d_in[10];
    const int* nbr3  = (const int*)d_in[11];
    const int* nbr4  = (const int*)d_in[12];
    const int* nbrd2 = (const int*)d_in[13];
    const int* nbrd3 = (const int*)d_in[14];
    const int* nbrd4 = (const int*)d_in[15];
    const int* nbri4 = (const int*)d_in[16];
    const int* nbri3 = (const int*)d_in[17];
    const int* nbri2 = (const int*)d_in[18];

    const int N1 = in_sizes[9]  / 27;
    const int N2 = in_sizes[10] / 27;
    const int N3 = in_sizes[11] / 27;
    const int N4 = in_sizes[12] / 27;

    float* pool = nullptr;
    cudaGetSymbolAddress((void**)&pool, g_pool);
    size_t off = 0;
    auto alloc = [&](size_t nfloats) {
        float* p = pool + off;
        off += (nfloats + 255) & ~(size_t)255;  // keep 1KB alignment
        return p;
    };
    auto bfalloc = [&](size_t nbf) { return (__nv_bfloat16*)alloc((nbf + 1) / 2); };

    // ---- Weight prep plan (all 31 slices -> one kernel) ----
    Tbl tbl{};
    long long elemAcc = 0, maxElem = 0;
    auto reg = [&](const float* src, int cin, int cinTot, int cinOff, int cout) -> long long {
        int nch = (cin >= 32) ? cin / 32 : 1;
        int ks = (cin >= 32) ? 2 : 1;
        long long nE = 27LL * nch * (cout / 8) * ks * 2 * 32;
        Ent& E = tbl.e[tbl.n++];
        E.src = src; E.dstOff = elemAcc; E.nElem = nE;
        E.cin = cin; E.cinTot = cinTot; E.cinOff = cinOff; E.cout = cout;
        E.nch = nch; E.ks = ks;
        long long r = elemAcc;
        elemAcc += nE;
        if (nE > maxElem) maxElem = nE;
        return r;
    };
    auto reg2 = [&](const float* src, int cinPh, int cout) -> long long {
        long long r = reg(src, cinPh, 2 * cinPh, 0, cout);
        reg(src, cinPh, 2 * cinPh, cinPh, cout);
        return r;
    };

    const long long W32S = 27LL * 32 * 32;
    const long long W64S = 27LL * 64 * 64;
    const long long W6432S = 27LL * 64 * 32;
    const long long W12864S = 27LL * 128 * 64;

    long long f_in  = reg(Win, 4, 4, 0, 32);
    long long f_w32[10], f_w64[10];
    for (int i = 0; i < 10; i++) f_w32[i] = reg(W32 + i * W32S, 32, 32, 0, 32);
    for (int i = 0; i < 10; i++) f_w64[i] = reg(W64 + i * W64S, 64, 64, 0, 64);
    long long f_d3  = reg(Wd3, 32, 32, 0, 64);
    long long f_xu3 = reg(W6432 + 0 * W6432S, 64, 64, 0, 32);   // xu3: 64 -> 32
    long long f_cat4 = reg2(W12864 + 0 * W12864S, 64, 64);
    long long f_cat3 = reg2(W12864 + 1 * W12864S, 64, 64);
    long long f_cat2 = reg2(W6432 + 1 * W6432S, 32, 32);
    long long f_cat1 = reg2(W6432 + 2 * W6432S, 32, 32);
    // total entries: 1 + 10 + 10 + 1 + 1 + 8 = 31  (Tbl holds 40)

    uint2* fragPool = (uint2*)alloc((size_t)elemAcc * 2);
    {
        unsigned bx = (unsigned)((maxElem + 255) / 256);
        prep_all_kernel<<<dim3(bx, (unsigned)tbl.n), 256>>>(tbl, fragPool);
    }

    // ---- Feature buffers (bf16 hi/lo pairs: N * 2*C halves) ----
    __nv_bfloat16* VF = bfalloc((size_t)N1 * 8);
    cvt_feat_kernel<<<(N1 * 4 + 255) / 256, 256>>>(vf, VF, N1, 4);

    __nv_bfloat16* L1a = bfalloc((size_t)N1 * 64);
    __nv_bfloat16* L1b = bfalloc((size_t)N1 * 64);
    __nv_bfloat16* L1c = bfalloc((size_t)N1 * 64);
    __nv_bfloat16* L1d = bfalloc((size_t)N1 * 64);
    __nv_bfloat16* L1e = bfalloc((size_t)N1 * 64);
    __nv_bfloat16* L2a = bfalloc((size_t)N2 * 64);
    __nv_bfloat16* L2b = bfalloc((size_t)N2 * 64);
    __nv_bfloat16* L2c = bfalloc((size_t)N2 * 64);
    __nv_bfloat16* L2d = bfalloc((size_t)N2 * 64);
    __nv_bfloat16* L3a = bfalloc((size_t)N3 * 128);
    __nv_bfloat16* L3b = bfalloc((size_t)N3 * 128);
    __nv_bfloat16* L3c = bfalloc((size_t)N3 * 128);
    __nv_bfloat16* L3d = bfalloc((size_t)N3 * 128);
    __nv_bfloat16* L4a = bfalloc((size_t)N4 * 128);
    __nv_bfloat16* L4b = bfalloc((size_t)N4 * 128);
    __nv_bfloat16* L4c = bfalloc((size_t)N4 * 128);

    auto b32 = [&](int j) { return bn32 + (long long)j * 64; };
    auto b64 = [&](int j) { return bn64 + (long long)j * 128; };
    float* nof = nullptr;
    __nv_bfloat16* nob = nullptr;

    // ---- Encoder ----
    CONV(4, 1, 32, M_BLOCK, false, VF, nob, nbr1, f_in, b32(0), nob, nof, L1a, N1);
    CONV(32, 1, 32, M_BLOCK, false, L1a, nob, nbr1, f_w32[0], b32(1), nob, nof, L1b, N1);   // x1
    CONV(32, 1, 32, M_BLOCK, false, L1b, nob, nbrd2, f_w32[1], b32(2), nob, nof, L2a, N2);
    CONV(32, 1, 32, M_BLOCK, false, L2a, nob, nbr2, f_w32[2], b32(3), nob, nof, L2b, N2);
    CONV(32, 1, 32, M_BLOCK, false, L2b, nob, nbr2, f_w32[3], b32(4), nob, nof, L2a, N2);   // x2
    CONV(32, 1, 64, M_BLOCK, false, L2a, nob, nbrd3, f_d3, b64(0), nob, nof, L3a, N3);
    CONV(64, 1, 64, M_BLOCK, false, L3a, nob, nbr3, f_w64[0], b64(1), nob, nof, L3b, N3);
    CONV(64, 1, 64, M_BLOCK, false, L3b, nob, nbr3, f_w64[1], b64(2), nob, nof, L3a, N3);   // x3
    CONV(64, 1, 64, M_BLOCK, false, L3a, nob, nbrd4, f_w64[2], b64(3), nob, nof, L4a, N4);
    CONV(64, 1, 64, M_BLOCK, false, L4a, nob, nbr4, f_w64[3], b64(4), nob, nof, L4b, N4);
    CONV(64, 1, 64, M_BLOCK, false, L4b, nob, nbr4, f_w64[4], b64(5), nob, nof, L4a, N4);   // x4

    // ---- Bottom: basic(x4) + concat conv + reduce ----
    CONV(64, 1, 64, M_BLOCK, false, L4a, nob, nbr4, f_w64[5], b64(6), nob, nof, L4b, N4);
    CONV(64, 1, 64, M_RES, false, L4b, nob, nbr4, f_w64[6], b64(7), L4a, nof, L4c, N4);     // t
    CONV(64, 2, 64, M_RED, false, L4a, L4c, nbr4, f_cat4, b64(11), nob, nof, L4b, N4);

    // ---- Decoder level 3 ----
    CONV(64, 1, 64, M_BLOCK, false, L4b, nob, nbri4, f_w64[7], b64(8), nob, nof, L3b, N3);  // xu4
    CONV(64, 1, 64, M_BLOCK, false, L3a, nob, nbr3, f_w64[8], b64(9), nob, nof, L3c, N3);
    CONV(64, 1, 64, M_RES, false, L3c, nob, nbr3, f_w64[9], b64(10), L3a, nof, L3d, N3);    // t
    CONV(64, 2, 64, M_RED, false, L3b, L3d, nbr3, f_cat3, b64(12), nob, nof, L3c, N3);

    // ---- Decoder level 2 ----
    CONV(64, 1, 32, M_BLOCK, false, L3c, nob, nbri3, f_xu3, b32(11), nob, nof, L2b, N2);    // xu3
    CONV(32, 1, 32, M_BLOCK, false, L2a, nob, nbr2, f_w32[4], b32(5), nob, nof, L2c, N2);
    CONV(32, 1, 32, M_RES, false, L2c, nob, nbr2, f_w32[5], b32(6), L2a, nof, L2d, N2);      // t
    CONV(32, 2, 32, M_RED, false, L2b, L2d, nbr2, f_cat2, b32(12), nob, nof, L2c, N2);

    // ---- Decoder level 1 ----
    CONV(32, 1, 32, M_BLOCK, false, L2c, nob, nbri2, f_w32[6], b32(7), nob, nof, L1c, N1);  // xu2
    CONV(32, 1, 32, M_BLOCK, false, L1b, nob, nbr1, f_w32[7], b32(8), nob, nof, L1d, N1);
    CONV(32, 1, 32, M_RES, false, L1d, nob, nbr1, f_w32[8], b32(9), L1b, nof, L1e, N1);     // t
    CONV(32, 2, 32, M_RED, false, L1c, L1e, nbr1, f_cat1, b32(13), nob, nof, L1d, N1);

    // ---- Output (f32) ----
    CONV(32, 1, 32, M_BLOCK, true, L1d, nob, nbr1, f_w32[9], b32(10), nob,
         (float*)d_out, nob, N1);
}

// round 16
// speedup vs baseline: 4.5485x; 1.0991x over previous
#include <cuda_runtime.h>
#include <cuda_bf16.h>
#include <cstdint>

// ---------------------------------------------------------------------------
// Static scratch pool (no cudaMalloc allowed).
// ---------------------------------------------------------------------------
#define POOL_FLOATS 420000000LL
__device__ __align__(1024) float g_pool[POOL_FLOATS];

enum { M_BLOCK = 0, M_RES = 1, M_RED = 2 };

// ---------------------------------------------------------------------------
// Baseline-PTX helpers (compute_103: ldmatrix + mma.sync + cp.async only;
// tcgen05 is arch-accelerated and NOT available under this harness target).
// ---------------------------------------------------------------------------
static __device__ __forceinline__ uint32_t smem_u32_of(const void* p) {
    uint32_t a;
    asm("{ .reg .u64 t; cvta.to.shared.u64 t, %1; cvt.u32.u64 %0, t; }" : "=r"(a) : "l"(p));
    return a;
}
static __device__ __forceinline__ void ldm_x4(uint32_t* r, uint32_t addr) {
    asm volatile("ldmatrix.sync.aligned.m8n8.x4.shared.b16 {%0,%1,%2,%3}, [%4];"
                 : "=r"(r[0]), "=r"(r[1]), "=r"(r[2]), "=r"(r[3]) : "r"(addr));
}
// D[16x8] += A[16x16](bf16,row) * B[16x8](bf16,col)
static __device__ __forceinline__ void mma16816(float* c, const uint32_t* a, const uint32_t* b) {
    asm volatile(
        "mma.sync.aligned.m16n8k16.row.col.f32.bf16.bf16.f32 "
        "{%0,%1,%2,%3}, {%4,%5,%6,%7}, {%8,%9}, {%0,%1,%2,%3};"
        : "+f"(c[0]), "+f"(c[1]), "+f"(c[2]), "+f"(c[3])
        : "r"(a[0]), "r"(a[1]), "r"(a[2]), "r"(a[3]), "r"(b[0]), "r"(b[1]));
}
// Split (x,y) into packed bf16x2 hi and lo (residual) words. Element 0 low 16.
static __device__ __forceinline__ void split2(float x, float y, uint32_t& hi, uint32_t& lo) {
    asm("cvt.rn.bf16x2.f32 %0, %1, %2;" : "=r"(hi) : "f"(y), "f"(x));
    float hx = __uint_as_float(hi << 16);
    float hy = __uint_as_float(hi & 0xffff0000u);
    asm("cvt.rn.bf16x2.f32 %0, %1, %2;" : "=r"(lo) : "f"(y - hy), "f"(x - hx));
}
static __device__ __forceinline__ void cp16(uint32_t dst, const void* src, uint32_t sz) {
    asm volatile("cp.async.ca.shared.global [%0], [%1], 16, %2;"
                 :: "r"(dst), "l"(src), "r"(sz) : "memory");
}
static __device__ __forceinline__ void cp8(uint32_t dst, const void* src, uint32_t sz) {
    asm volatile("cp.async.ca.shared.global [%0], [%1], 8, %2;"
                 :: "r"(dst), "l"(src), "r"(sz) : "memory");
}
static __device__ __forceinline__ void cp_commit() {
    asm volatile("cp.async.commit_group;" ::: "memory");
}
template<int W>
static __device__ __forceinline__ void cp_wait() {
    asm volatile("cp.async.wait_group %0;" :: "n"(W) : "memory");
}

// ---------------------------------------------------------------------------
// Convert f32 features -> bf16 hi/lo pairs: dst row r = [hi(C) | lo(C)].
// ---------------------------------------------------------------------------
__global__ void cvt_feat_kernel(const float* __restrict__ src, __nv_bfloat16* __restrict__ dst,
                                int N, int C) {
    int t = blockIdx.x * blockDim.x + threadIdx.x;
    if (t >= N * C) return;
    int r = t / C, c = t - r * C;
    float v = src[t];
    __nv_bfloat16 h = __float2bfloat16(v);
    dst[(size_t)r * 2 * C + c] = h;
    dst[(size_t)r * 2 * C + C + c] = __float2bfloat16(v - __bfloat162float(h));
}

// ---------------------------------------------------------------------------
// Batched weight prep: all conv weights -> mma B-fragment order, one launch.
// Entry element order: [k][ch][j][s][sel(hi/lo)][lane], each element one
// uint2 = {b0, b1} for mma.m16n8k16 (B col-major, thread 'lane').
//   b0 = pack(B[kk][n], B[kk+1][n]),  b1 = same rows +8
//   n = j*8 + lane/4,  kk = s*16 + (lane%4)*2,  B[c][n] = W[cinOff+ch*32+c][n]
// ---------------------------------------------------------------------------
struct Ent {
    const float* src;
    long long dstOff;   // uint2 units into frag pool
    long long nElem;
    int cin, cinTot, cinOff, cout, nch, ks;
};
struct Tbl {
    Ent e[40];
    int n;
};

__global__ void prep_all_kernel(Tbl tbl, uint2* __restrict__ pool) {
    const Ent E = tbl.e[blockIdx.y];
    const int NT = E.cout / 8;
    for (long long i = (long long)blockIdx.x * blockDim.x + threadIdx.x; i < E.nElem;
         i += (long long)gridDim.x * blockDim.x) {
        const int lane = (int)(i & 31);
        long long r = i >> 5;
        const int sel = (int)(r & 1); r >>= 1;
        const int s = (int)(r % E.ks); r /= E.ks;
        const int j = (int)(r % NT); r /= NT;
        const int ch = (int)(r % E.nch);
        const int k = (int)(r / E.nch);
        const int n = j * 8 + (lane >> 2);
        const int kk = s * 16 + (lane & 3) * 2;
        const int cb = ch * 32;
        auto val = [&](int c) -> float {
            int cg = cb + c;
            return (cg < E.cin)
                       ? E.src[((size_t)k * E.cinTot + E.cinOff + cg) * E.cout + n]
                       : 0.0f;
        };
        float a0 = val(kk), a1 = val(kk + 1), c0 = val(kk + 8), c1 = val(kk + 9);
        uint32_t h, l, w0, w1;
        split2(a0, a1, h, l);
        w0 = sel ? l : h;
        split2(c0, c1, h, l);
        w1 = sel ? l : h;
        pool[E.dstOff + i] = make_uint2(w0, w1);
    }
}

// ---------------------------------------------------------------------------
// Sparse gather-conv: bf16 split precision (3 MMAs ~ fp32).
// CTA = 128 rows, 4 warps; warp w owns rows 32w..32w+31. Gather is
// 8-lanes-per-row: each cp.async touches 4 CONTIGUOUS 128B feature rows
// (vs 32 scattered rows before) -> ~8x fewer L1 wavefronts.
// No CTA barriers in mainloop (cp.async groups + __syncwarp).
// B fragments come straight from gmem (L1-resident), A via smem ldmatrix.
// ---------------------------------------------------------------------------
template<int CIN, int NPHASE, int COUT, int MODE, bool OUTF32>
__global__ void __launch_bounds__(128, 4)
conv_mma_kernel(const __nv_bfloat16* __restrict__ featA,
                const __nv_bfloat16* __restrict__ featB,
                const int* __restrict__ nbr,
                const uint2* __restrict__ frag,
                const float* __restrict__ sb,
                const __nv_bfloat16* __restrict__ resbf,
                float* __restrict__ outf,
                __nv_bfloat16* __restrict__ outbf, int N) {
    constexpr int CPAD = (CIN >= 32) ? 32 : 16;
    constexpr int NCH = (CIN >= 32) ? CIN / 32 : 1;
    constexpr int KS = CPAD / 16;
    constexpr int STR = CPAD + 8;               // halves per smem A row
    constexpr int NT = COUT / 8;
    constexpr int IPK = NPHASE * NCH;
    constexpr int TOT = 27 * IPK;
    constexpr size_t FRAG_IT = (size_t)NT * KS * 2 * 32;   // uint2 per (k,ch)
    constexpr size_t PH_STRIDE = (size_t)27 * NCH * FRAG_IT;

    constexpr uint32_t A_HALF = 128u * STR * 2;  // one hi (or lo) A tile, bytes
    constexpr uint32_t ABUF = 2 * A_HALF;        // hi+lo
    constexpr uint32_t OFF_NBR = 2 * ABUF;

    extern __shared__ __align__(16) char smem[];
    const uint32_t sbase = smem_u32_of(smem);
    int* sNbr = (int*)(smem + OFF_NBR);

    const int tid = threadIdx.x;
    const int wid = tid >> 5;
    const int lane = tid & 31;
    const long long r0 = (long long)blockIdx.x * 128;

    // Stage neighbor table (coalesced); zero A buffers if K padded (CIN=4).
    const long long NI = (long long)N * 27;
    for (int i = tid; i < 128 * 27; i += 128) {
        long long g = r0 * 27 + i;
        sNbr[i] = (g < NI) ? nbr[g] : -1;
    }
    if constexpr (CIN < 32) {
        for (int i = tid; i < (int)(2 * ABUF / 16); i += 128)
            ((float4*)smem)[i] = make_float4(0.f, 0.f, 0.f, 0.f);
    }
    __syncthreads();  // only CTA barrier in the kernel

    auto issue = [&](int it) {
        const int k = it / IPK;
        const int rem = it - k * IPK;
        const int ph = (NPHASE > 1) ? rem / NCH : 0;
        const int ch = (NPHASE > 1) ? rem - ph * NCH : rem;
        const uint32_t b = (uint32_t)(it & 1);
        const __nv_bfloat16* f = (NPHASE > 1 && ph) ? featB : featA;
        if constexpr (CIN >= 32) {
            // 8 lanes per row: part = lane&7 (0-3 hi chunk, 4-7 lo chunk),
            // 4 consecutive rows per step, 8 steps cover the warp's 32 rows.
            const int part = lane & 7;
            const int isLo = part >> 2;         // 0 = hi, 1 = lo
            const int p4 = part & 3;
            const int rwb = wid * 32 + (lane >> 3);
#pragma unroll
            for (int u = 0; u < 8; u++) {
                const int rw = rwb + u * 4;     // row within CTA (this warp's)
                const int idx = sNbr[rw * 27 + k];
                const uint32_t sz = (idx >= 0) ? 16u : 0u;
                const __nv_bfloat16* src = f + (size_t)(idx >= 0 ? idx : 0) * 2 * CIN +
                                           (size_t)ch * 32 + (isLo ? CIN : 0) + p4 * 8;
                const uint32_t dst = sbase + b * ABUF + (isLo ? A_HALF : 0u) +
                                     (uint32_t)rw * (STR * 2) + (uint32_t)p4 * 16;
                cp16(dst, src, sz);
            }
        } else {
            const int idx = sNbr[tid * 27 + k];
            const uint32_t sz = (idx >= 0) ? 8u : 0u;
            const __nv_bfloat16* s_ = f + (size_t)(idx >= 0 ? idx : 0) * 8;
            const uint32_t dh = sbase + b * ABUF + (uint32_t)tid * (STR * 2);
            cp8(dh, s_, sz);
            cp8(dh + A_HALF, s_ + 4, sz);
        }
        cp_commit();
    };

    float acc[2][NT][4];
#pragma unroll
    for (int rt = 0; rt < 2; rt++)
#pragma unroll
        for (int j = 0; j < NT; j++)
#pragma unroll
            for (int u = 0; u < 4; u++) acc[rt][j][u] = 0.0f;

    issue(0);
    for (int it = 0; it < TOT; ++it) {
        const int k = it / IPK;
        const int rem = it - k * IPK;
        const int ph = (NPHASE > 1) ? rem / NCH : 0;
        const int ch = (NPHASE > 1) ? rem - ph * NCH : rem;
        if (it + 1 < TOT) {
            issue(it + 1);
            cp_wait<1>();
        } else {
            cp_wait<0>();
        }
        __syncwarp();  // warp-wide visibility of this warp's gathered rows

        const uint2* fb = frag + ((NPHASE > 1) ? (size_t)ph * PH_STRIDE : 0) +
                          (size_t)(k * NCH + ch) * FRAG_IT;
        const uint32_t abase = sbase + (uint32_t)(it & 1) * ABUF;
        const uint32_t rowbase = (uint32_t)wid * 32;
#pragma unroll
        for (int s = 0; s < KS; s++) {
            uint32_t ahi[2][4], alo[2][4];
#pragma unroll
            for (int rt = 0; rt < 2; rt++) {
                const uint32_t arow = rowbase + rt * 16 + (lane & 15);
                const uint32_t acol = (uint32_t)s * 16 + (((uint32_t)lane >> 4) << 3);
                const uint32_t aoff = (arow * STR + acol) * 2;
                ldm_x4(ahi[rt], abase + aoff);
                ldm_x4(alo[rt], abase + A_HALF + aoff);
            }
#pragma unroll
            for (int j = 0; j < NT; j++) {
                const uint2 bh = __ldg(fb + ((size_t)(j * KS + s) * 2 + 0) * 32 + lane);
                const uint2 bl = __ldg(fb + ((size_t)(j * KS + s) * 2 + 1) * 32 + lane);
                const uint32_t bhi[2] = {bh.x, bh.y};
                const uint32_t blo[2] = {bl.x, bl.y};
#pragma unroll
                for (int rt = 0; rt < 2; rt++) {
                    mma16816(acc[rt][j], ahi[rt], bhi);
                    mma16816(acc[rt][j], ahi[rt], blo);
                    mma16816(acc[rt][j], alo[rt], bhi);
                }
            }
        }
        __syncwarp();  // all lanes done reading buffer before it is re-filled
    }

    // Epilogue. Fragment (rt,j): c0,c1 -> row wid*32+rt*16+lane/4, cols n0,n0+1;
    // c2,c3 -> row +8.
    const float* scale = sb;
    const float* bias = sb + COUT;
#pragma unroll
    for (int j = 0; j < NT; j++) {
        const int n0 = j * 8 + 2 * (lane & 3);
        const float sc0 = scale[n0], sc1 = scale[n0 + 1];
        const float bi0 = bias[n0], bi1 = bias[n0 + 1];
#pragma unroll
        for (int rt = 0; rt < 2; rt++)
#pragma unroll
            for (int h = 0; h < 2; h++) {
                const long long r = r0 + wid * 32 + rt * 16 + (lane >> 2) + h * 8;
                if (r >= N) continue;
                float v0 = acc[rt][j][2 * h + 0] * sc0 + bi0;
                float v1 = acc[rt][j][2 * h + 1] * sc1 + bi1;
                if constexpr (MODE == M_RES) {
                    const __nv_bfloat16* rb = resbf + (size_t)r * 2 * COUT;
                    __nv_bfloat162 rh = *(const __nv_bfloat162*)(rb + n0);
                    __nv_bfloat162 rl = *(const __nv_bfloat162*)(rb + COUT + n0);
                    v0 += __bfloat162float(rh.x) + __bfloat162float(rl.x);
                    v1 += __bfloat162float(rh.y) + __bfloat162float(rl.y);
                }
                v0 = fmaxf(v0, 0.0f);
                v1 = fmaxf(v1, 0.0f);
                if constexpr (MODE == M_RED) {
#pragma unroll
                    for (int u = 0; u < 2; u++) {
                        const int c = n0 + u;
                        const __nv_bfloat16* src;
                        int cc;
                        if (2 * c + 1 < CIN) { src = featA + (size_t)r * 2 * CIN; cc = 2 * c; }
                        else { src = featB + (size_t)r * 2 * CIN; cc = 2 * c - CIN; }
                        __nv_bfloat162 hh = *(const __nv_bfloat162*)(src + cc);
                        __nv_bfloat162 ll = *(const __nv_bfloat162*)(src + CIN + cc);
                        float rsum = __bfloat162float(hh.x) + __bfloat162float(ll.x) +
                                     __bfloat162float(hh.y) + __bfloat162float(ll.y);
                        if (u == 0) v0 += rsum; else v1 += rsum;
                    }
                }
                if constexpr (OUTF32) {
                    *(float2*)(outf + (size_t)r * COUT + n0) = make_float2(v0, v1);
                } else {
                    uint32_t hw, lw;
                    split2(v0, v1, hw, lw);
                    *(uint32_t*)(outbf + (size_t)r * 2 * COUT + n0) = hw;
                    *(uint32_t*)(outbf + (size_t)r * 2 * COUT + COUT + n0) = lw;
                }
            }
    }
}

// ---------------------------------------------------------------------------
// Host orchestration
// ---------------------------------------------------------------------------
#define CONV(CIN_, NPH_, CO_, MO_, OUTF_, fa, fb, nb, fragoff, sbp, rs, outf_, outbf_, n)     \
    do {                                                                                      \
        constexpr int STR_ = (((CIN_) >= 32) ? 32 : 16) + 8;                                  \
        auto kfn = conv_mma_kernel<CIN_, NPH_, CO_, MO_, OUTF_>;                              \
        constexpr size_t sh = (size_t)2 * (2 * 128 * STR_ * 2) + (size_t)128 * 27 * 4;        \
        cudaFuncSetAttribute(kfn, cudaFuncAttributeMaxDynamicSharedMemorySize, (int)sh);      \
        kfn<<<(unsigned)(((n) + 127) / 128), 128, sh>>>(fa, fb, nb, fragPool + (fragoff),     \
                                                        sbp, rs, outf_, outbf_, n);           \
    } while (0)

extern "C" void kernel_launch(void* const* d_in, const int* in_sizes, int n_in,
                              void* d_out, int out_size) {
    (void)n_in; (void)out_size;
    const float* vf     = (const float*)d_in[0];
    const float* Win    = (const float*)d_in[1];
    const float* W32    = (const float*)d_in[2];
    const float* W64    = (const float*)d_in[3];
    const float* Wd3    = (const float*)d_in[4];
    const float* W6432  = (const float*)d_in[5];
    const float* W12864 = (const float*)d_in[6];
    const float* bn32   = (const float*)d_in[7];
    const float* bn64   = (const float*)d_in[8];
    const int* nbr1  = (const int*)d_in[9];
    const int* nbr2  = (const int*)d_in[10];
    const int* nbr3  = (const int*)d_in[11];
    const int* nbr4  = (const int*)d_in[12];
    const int* nbrd2 = (const int*)d_in[13];
    const int* nbrd3 = (const int*)d_in[14];
    const int* nbrd4 = (const int*)d_in[15];
    const int* nbri4 = (const int*)d_in[16];
    const int* nbri3 = (const int*)d_in[17];
    const int* nbri2 = (const int*)d_in[18];

    const int N1 = in_sizes[9]  / 27;
    const int N2 = in_sizes[10] / 27;
    const int N3 = in_sizes[11] / 27;
    const int N4 = in_sizes[12] / 27;

    float* pool = nullptr;
    cudaGetSymbolAddress((void**)&pool, g_pool);
    size_t off = 0;
    auto alloc = [&](size_t nfloats) {
        float* p = pool + off;
        off += (nfloats + 255) & ~(size_t)255;  // keep 1KB alignment
        return p;
    };
    auto bfalloc = [&](size_t nbf) { return (__nv_bfloat16*)alloc((nbf + 1) / 2); };

    // ---- Weight prep plan (all 31 slices -> one kernel) ----
    Tbl tbl{};
    long long elemAcc = 0, maxElem = 0;
    auto reg = [&](const float* src, int cin, int cinTot, int cinOff, int cout) -> long long {
        int nch = (cin >= 32) ? cin / 32 : 1;
        int ks = (cin >= 32) ? 2 : 1;
        long long nE = 27LL * nch * (cout / 8) * ks * 2 * 32;
        Ent& E = tbl.e[tbl.n++];
        E.src = src; E.dstOff = elemAcc; E.nElem = nE;
        E.cin = cin; E.cinTot = cinTot; E.cinOff = cinOff; E.cout = cout;
        E.nch = nch; E.ks = ks;
        long long r = elemAcc;
        elemAcc += nE;
        if (nE > maxElem) maxElem = nE;
        return r;
    };
    auto reg2 = [&](const float* src, int cinPh, int cout) -> long long {
        long long r = reg(src, cinPh, 2 * cinPh, 0, cout);
        reg(src, cinPh, 2 * cinPh, cinPh, cout);
        return r;
    };

    const long long W32S = 27LL * 32 * 32;
    const long long W64S = 27LL * 64 * 64;
    const long long W6432S = 27LL * 64 * 32;
    const long long W12864S = 27LL * 128 * 64;

    long long f_in  = reg(Win, 4, 4, 0, 32);
    long long f_w32[10], f_w64[10];
    for (int i = 0; i < 10; i++) f_w32[i] = reg(W32 + i * W32S, 32, 32, 0, 32);
    for (int i = 0; i < 10; i++) f_w64[i] = reg(W64 + i * W64S, 64, 64, 0, 64);
    long long f_d3  = reg(Wd3, 32, 32, 0, 64);
    long long f_xu3 = reg(W6432 + 0 * W6432S, 64, 64, 0, 32);   // xu3: 64 -> 32
    long long f_cat4 = reg2(W12864 + 0 * W12864S, 64, 64);
    long long f_cat3 = reg2(W12864 + 1 * W12864S, 64, 64);
    long long f_cat2 = reg2(W6432 + 1 * W6432S, 32, 32);
    long long f_cat1 = reg2(W6432 + 2 * W6432S, 32, 32);
    // total entries: 1 + 10 + 10 + 1 + 1 + 8 = 31  (Tbl holds 40)

    uint2* fragPool = (uint2*)alloc((size_t)elemAcc * 2);
    {
        unsigned bx = (unsigned)((maxElem + 255) / 256);
        prep_all_kernel<<<dim3(bx, (unsigned)tbl.n), 256>>>(tbl, fragPool);
    }

    // ---- Feature buffers (bf16 hi/lo pairs: N * 2*C halves) ----
    __nv_bfloat16* VF = bfalloc((size_t)N1 * 8);
    cvt_feat_kernel<<<(N1 * 4 + 255) / 256, 256>>>(vf, VF, N1, 4);

    __nv_bfloat16* L1a = bfalloc((size_t)N1 * 64);
    __nv_bfloat16* L1b = bfalloc((size_t)N1 * 64);
    __nv_bfloat16* L1c = bfalloc((size_t)N1 * 64);
    __nv_bfloat16* L1d = bfalloc((size_t)N1 * 64);
    __nv_bfloat16* L1e = bfalloc((size_t)N1 * 64);
    __nv_bfloat16* L2a = bfalloc((size_t)N2 * 64);
    __nv_bfloat16* L2b = bfalloc((size_t)N2 * 64);
    __nv_bfloat16* L2c = bfalloc((size_t)N2 * 64);
    __nv_bfloat16* L2d = bfalloc((size_t)N2 * 64);
    __nv_bfloat16* L3a = bfalloc((size_t)N3 * 128);
    __nv_bfloat16* L3b = bfalloc((size_t)N3 * 128);
    __nv_bfloat16* L3c = bfalloc((size_t)N3 * 128);
    __nv_bfloat16* L3d = bfalloc((size_t)N3 * 128);
    __nv_bfloat16* L4a = bfalloc((size_t)N4 * 128);
    __nv_bfloat16* L4b = bfalloc((size_t)N4 * 128);
    __nv_bfloat16* L4c = bfalloc((size_t)N4 * 128);

    auto b32 = [&](int j) { return bn32 + (long long)j * 64; };
    auto b64 = [&](int j) { return bn64 + (long long)j * 128; };
    float* nof = nullptr;
    __nv_bfloat16* nob = nullptr;

    // ---- Encoder ----
    CONV(4, 1, 32, M_BLOCK, false, VF, nob, nbr1, f_in, b32(0), nob, nof, L1a, N1);
    CONV(32, 1, 32, M_BLOCK, false, L1a, nob, nbr1, f_w32[0], b32(1), nob, nof, L1b, N1);   // x1
    CONV(32, 1, 32, M_BLOCK, false, L1b, nob, nbrd2, f_w32[1], b32(2), nob, nof, L2a, N2);
    CONV(32, 1, 32, M_BLOCK, false, L2a, nob, nbr2, f_w32[2], b32(3), nob, nof, L2b, N2);
    CONV(32, 1, 32, M_BLOCK, false, L2b, nob, nbr2, f_w32[3], b32(4), nob, nof, L2a, N2);   // x2
    CONV(32, 1, 64, M_BLOCK, false, L2a, nob, nbrd3, f_d3, b64(0), nob, nof, L3a, N3);
    CONV(64, 1, 64, M_BLOCK, false, L3a, nob, nbr3, f_w64[0], b64(1), nob, nof, L3b, N3);
    CONV(64, 1, 64, M_BLOCK, false, L3b, nob, nbr3, f_w64[1], b64(2), nob, nof, L3a, N3);   // x3
    CONV(64, 1, 64, M_BLOCK, false, L3a, nob, nbrd4, f_w64[2], b64(3), nob, nof, L4a, N4);
    CONV(64, 1, 64, M_BLOCK, false, L4a, nob, nbr4, f_w64[3], b64(4), nob, nof, L4b, N4);
    CONV(64, 1, 64, M_BLOCK, false, L4b, nob, nbr4, f_w64[4], b64(5), nob, nof, L4a, N4);   // x4

    // ---- Bottom: basic(x4) + concat conv + reduce ----
    CONV(64, 1, 64, M_BLOCK, false, L4a, nob, nbr4, f_w64[5], b64(6), nob, nof, L4b, N4);
    CONV(64, 1, 64, M_RES, false, L4b, nob, nbr4, f_w64[6], b64(7), L4a, nof, L4c, N4);     // t
    CONV(64, 2, 64, M_RED, false, L4a, L4c, nbr4, f_cat4, b64(11), nob, nof, L4b, N4);

    // ---- Decoder level 3 ----
    CONV(64, 1, 64, M_BLOCK, false, L4b, nob, nbri4, f_w64[7], b64(8), nob, nof, L3b, N3);  // xu4
    CONV(64, 1, 64, M_BLOCK, false, L3a, nob, nbr3, f_w64[8], b64(9), nob, nof, L3c, N3);
    CONV(64, 1, 64, M_RES, false, L3c, nob, nbr3, f_w64[9], b64(10), L3a, nof, L3d, N3);    // t
    CONV(64, 2, 64, M_RED, false, L3b, L3d, nbr3, f_cat3, b64(12), nob, nof, L3c, N3);

    // ---- Decoder level 2 ----
    CONV(64, 1, 32, M_BLOCK, false, L3c, nob, nbri3, f_xu3, b32(11), nob, nof, L2b, N2);    // xu3
    CONV(32, 1, 32, M_BLOCK, false, L2a, nob, nbr2, f_w32[4], b32(5), nob, nof, L2c, N2);
    CONV(32, 1, 32, M_RES, false, L2c, nob, nbr2, f_w32[5], b32(6), L2a, nof, L2d, N2);      // t
    CONV(32, 2, 32, M_RED, false, L2b, L2d, nbr2, f_cat2, b32(12), nob, nof, L2c, N2);

    // ---- Decoder level 1 ----
    CONV(32, 1, 32, M_BLOCK, false, L2c, nob, nbri2, f_w32[6], b32(7), nob, nof, L1c, N1);  // xu2
    CONV(32, 1, 32, M_BLOCK, false, L1b, nob, nbr1, f_w32[7], b32(8), nob, nof, L1d, N1);
    CONV(32, 1, 32, M_RES, false, L1d, nob, nbr1, f_w32[8], b32(9), L1b, nof, L1e, N1);     // t
    CONV(32, 2, 32, M_RED, false, L1c, L1e, nbr1, f_cat1, b32(13), nob, nof, L1d, N1);

    // ---- Output (f32) ----
    CONV(32, 1, 32, M_BLOCK, true, L1d, nob, nbr1, f_w32[9], b32(10), nob,
         (float*)d_out, nob, N1);
}